// round 3
// baseline (speedup 1.0000x reference)
#include <cuda_runtime.h>
#include <cuda_bf16.h>

// Problem constants
#define B    256
#define T    256
#define NQ   1000
#define DK   128
#define DV   128
#define CC   32
#define TOUT 255
#define NROWS (B * TOUT)         // 65280

typedef unsigned long long u64;

// ---------------- packed f32x2 helpers (sm_103a) --------------------------
__device__ __forceinline__ u64 pack2(float lo, float hi) {
    u64 r; asm("mov.b64 %0, {%1, %2};" : "=l"(r) : "f"(lo), "f"(hi)); return r;
}
__device__ __forceinline__ void unpack2(u64 v, float& lo, float& hi) {
    asm("mov.b64 {%0, %1}, %2;" : "=f"(lo), "=f"(hi) : "l"(v));
}
__device__ __forceinline__ u64 fma2(u64 a, u64 b, u64 c) {
    u64 d; asm("fma.rn.f32x2 %0, %1, %2, %3;" : "=l"(d) : "l"(a), "l"(b), "l"(c)); return d;
}

// ---------------- device scratch ------------------------------------------
__device__ __align__(16) float g_wt[NQ * CC];       // softmax(k_emb @ Mk)
__device__ __align__(16) float g_g [NQ * DK];       // k_emb @ f_W[128:] + f_b
__device__ __align__(16) float g_et[2 * NQ * DV];   // sigmoid(v_emb @ e_W + e_b)
__device__ __align__(16) float g_at[2 * NQ * DV];   // tanh(v_emb @ a_W + a_b)
__device__ __align__(16) float g_rt[NROWS * DV];    // rt scratch
__device__ __align__(16) u64   g_fw2[(DK / 2) * DK]; // f_W rows 0..127 packed by i-pair

// ---------------- precompute: wt = softmax(k_emb @ Mk) --------------------
__global__ void pre_wt_kernel(const float* __restrict__ k_emb,
                              const float* __restrict__ Mk) {
    int warp = threadIdx.x >> 5;
    int lane = threadIdx.x & 31;
    int q = blockIdx.x * 4 + warp;
    if (q >= NQ) return;
    const float* krow = k_emb + q * DK;
    float acc = 0.f;
    #pragma unroll 8
    for (int k = 0; k < DK; k++)
        acc = fmaf(__ldg(krow + k), __ldg(Mk + k * CC + lane), acc);
    float mx = acc;
    #pragma unroll
    for (int off = 16; off; off >>= 1)
        mx = fmaxf(mx, __shfl_xor_sync(0xffffffffu, mx, off));
    float e = expf(acc - mx);
    float s = e;
    #pragma unroll
    for (int off = 16; off; off >>= 1)
        s += __shfl_xor_sync(0xffffffffu, s, off);
    g_wt[q * CC + lane] = e / s;
}

// ---------------- precompute: pack f_W upper half into u64 i-pairs ---------
__global__ void pre_pack_kernel(const float* __restrict__ f_W) {
    int idx = blockIdx.x * 256 + threadIdx.x;   // 0..8191
    int ip = idx >> 7;
    int j  = idx & 127;
    g_fw2[idx] = pack2(__ldg(f_W + (2 * ip) * DK + j),
                       __ldg(f_W + (2 * ip + 1) * DK + j));
}

// ---------------- precompute: g = k_emb @ f_W[128:] + f_b (16-row tiles) ---
#define PG_ROWS 16
__global__ void __launch_bounds__(256)
pre_g_kernel(const float* __restrict__ k_emb,
             const float* __restrict__ f_W,
             const float* __restrict__ f_b) {
    __shared__ __align__(16) float xs[PG_ROWS * DK];
    int tid = threadIdx.x;
    int j   = tid & 127;
    int rh  = tid >> 7;
    int row0 = blockIdx.x * PG_ROWS;

    // stage (clamped for tail block)
    #pragma unroll
    for (int u = 0; u < 2; u++) {
        int idx = tid + u * 256;                 // float4 index, 512 total
        int r   = idx >> 5;                      // 32 float4 per row
        int gr  = row0 + r; if (gr >= NQ) gr = NQ - 1;
        reinterpret_cast<float4*>(xs)[idx] =
            __ldg(reinterpret_cast<const float4*>(k_emb + gr * DK) + (idx & 31));
    }
    __syncthreads();

    float acc[8];
    float fb = __ldg(f_b + j);
    #pragma unroll
    for (int r = 0; r < 8; r++) acc[r] = fb;

    const float* xb = xs + rh * 8 * DK;
    #pragma unroll 4
    for (int k = 0; k < DK; k += 4) {
        float w0 = __ldg(f_W + (DK + k + 0) * DK + j);
        float w1 = __ldg(f_W + (DK + k + 1) * DK + j);
        float w2 = __ldg(f_W + (DK + k + 2) * DK + j);
        float w3 = __ldg(f_W + (DK + k + 3) * DK + j);
        #pragma unroll
        for (int r = 0; r < 8; r++) {
            float4 xv = *reinterpret_cast<const float4*>(xb + r * DK + k);
            acc[r] = fmaf(xv.x, w0, acc[r]);
            acc[r] = fmaf(xv.y, w1, acc[r]);
            acc[r] = fmaf(xv.z, w2, acc[r]);
            acc[r] = fmaf(xv.w, w3, acc[r]);
        }
    }
    #pragma unroll
    for (int r = 0; r < 8; r++) {
        int gr = row0 + rh * 8 + r;
        if (gr < NQ) g_g[gr * DK + j] = acc[r];
    }
}

// ---------------- precompute: et/at (16-row tiles over 2000 rows) ----------
#define EA_ROWS 16
__global__ void __launch_bounds__(256)
pre_ea_kernel(const float* __restrict__ v_emb,
              const float* __restrict__ e_W,
              const float* __restrict__ e_b,
              const float* __restrict__ a_W,
              const float* __restrict__ a_b) {
    __shared__ __align__(16) float xs[EA_ROWS * DV];
    int tid = threadIdx.x;
    int j   = tid & 127;
    int rh  = tid >> 7;
    int row0 = blockIdx.x * EA_ROWS;             // 125 blocks, exact

    #pragma unroll
    for (int u = 0; u < 2; u++) {
        int idx = tid + u * 256;
        reinterpret_cast<float4*>(xs)[idx] =
            __ldg(reinterpret_cast<const float4*>(v_emb + row0 * DV) + idx);
    }
    __syncthreads();

    float acce[8], acca[8];
    float eb = __ldg(e_b + j), ab = __ldg(a_b + j);
    #pragma unroll
    for (int r = 0; r < 8; r++) { acce[r] = eb; acca[r] = ab; }

    const float* xb = xs + rh * 8 * DV;
    #pragma unroll 2
    for (int k = 0; k < DV; k += 4) {
        float we0 = __ldg(e_W + (k + 0) * DV + j);
        float we1 = __ldg(e_W + (k + 1) * DV + j);
        float we2 = __ldg(e_W + (k + 2) * DV + j);
        float we3 = __ldg(e_W + (k + 3) * DV + j);
        float wa0 = __ldg(a_W + (k + 0) * DV + j);
        float wa1 = __ldg(a_W + (k + 1) * DV + j);
        float wa2 = __ldg(a_W + (k + 2) * DV + j);
        float wa3 = __ldg(a_W + (k + 3) * DV + j);
        #pragma unroll
        for (int r = 0; r < 8; r++) {
            float4 xv = *reinterpret_cast<const float4*>(xb + r * DV + k);
            acce[r] = fmaf(xv.x, we0, acce[r]);
            acce[r] = fmaf(xv.y, we1, acce[r]);
            acce[r] = fmaf(xv.z, we2, acce[r]);
            acce[r] = fmaf(xv.w, we3, acce[r]);
            acca[r] = fmaf(xv.x, wa0, acca[r]);
            acca[r] = fmaf(xv.y, wa1, acca[r]);
            acca[r] = fmaf(xv.z, wa2, acca[r]);
            acca[r] = fmaf(xv.w, wa3, acca[r]);
        }
    }
    #pragma unroll
    for (int r = 0; r < 8; r++) {
        int gr = row0 + rh * 8 + r;
        g_et[gr * DV + j] = 1.0f / (1.0f + expf(-acce[r]));
        g_at[gr * DV + j] = tanhf(acca[r]);
    }
}

// ---------------- sequential scan (4-way c-split, 512 threads) -------------
// Warp layout: lane = h*8 + dl, h in [0,4) owns c in [h*8, h*8+8) (4 pairs),
// dl in [0,8) selects d = warp*8 + dl. rt reduced via shfl_xor(8),(16).

__device__ __forceinline__ void scan_load4(int s, int q, int d, int h,
                                           u64 W[4], float& e, float& a) {
    const ulonglong2* wp =
        reinterpret_cast<const ulonglong2*>(g_wt + s * CC + h * 8);
    ulonglong2 v0 = __ldg(wp);
    ulonglong2 v1 = __ldg(wp + 1);
    W[0] = v0.x; W[1] = v0.y; W[2] = v1.x; W[3] = v1.y;
    e = __ldg(g_et + q * DV + d);
    a = __ldg(g_at + q * DV + d);
}

__device__ __forceinline__ float scan_step4(u64 m2[4], const u64 W[4],
                                            float e, float a) {
    u64 en2 = pack2(-e, -e);
    u64 a2  = pack2(a, a);
    u64 acc0 = 0ull, acc1 = 0ull;
    #pragma unroll
    for (int p = 0; p < 4; p++) {
        u64 mo = m2[p];
        if (p & 1) acc1 = fma2(W[p], mo, acc1);
        else       acc0 = fma2(W[p], mo, acc0);
        u64 tmp = fma2(mo, en2, a2);       // a - e*m
        m2[p] = fma2(W[p], tmp, mo);       // m + w*(a - e*m)
    }
    float x0, x1, y0, y1;
    unpack2(acc0, x0, x1);
    unpack2(acc1, y0, y1);
    float s = (x0 + y0) + (x1 + y1);
    s += __shfl_xor_sync(0xffffffffu, s, 8);
    s += __shfl_xor_sync(0xffffffffu, s, 16);
    return s;
}

__global__ void __launch_bounds__(512, 2)
scan_kernel(const int* __restrict__ skills,
            const int* __restrict__ responses,
            const float* __restrict__ Mv0) {
    int b   = blockIdx.x;
    int tid = threadIdx.x;
    int w   = tid >> 5;
    int l   = tid & 31;
    int dl  = l & 7;
    int h   = l >> 3;
    int d   = w * 8 + dl;

    u64 m2[4];
    #pragma unroll
    for (int p = 0; p < 4; p++) {
        int c = h * 8 + 2 * p;
        m2[p] = pack2(__ldg(Mv0 + c * DV + d), __ldg(Mv0 + (c + 1) * DV + d));
    }

    const int* srow = skills + b * T;
    const int* rrow = responses + b * T;
    float* rtp = g_rt + (b * TOUT) * DV + d;

    int sn = __ldg(srow);
    int qn = sn + NQ * __ldg(rrow);
    u64 WA[4]; float eA, aA;
    scan_load4(sn, qn, d, h, WA, eA, aA);
    sn = __ldg(srow + 1);
    qn = sn + NQ * __ldg(rrow + 1);

    for (int t = 0; t < TOUT - 1; t += 2) {
        u64 WB[4]; float eB, aB;
        scan_load4(sn, qn, d, h, WB, eB, aB);
        sn = __ldg(srow + t + 2);
        qn = sn + NQ * __ldg(rrow + t + 2);

        float s0 = scan_step4(m2, WA, eA, aA);
        if (h == 0) rtp[t * DV] = s0;

        scan_load4(sn, qn, d, h, WA, eA, aA);
        sn = __ldg(srow + t + 3);                 // t+3 <= 255, in range
        qn = sn + NQ * __ldg(rrow + t + 3);

        float s1 = scan_step4(m2, WB, eB, aB);
        if (h == 0) rtp[(t + 1) * DV] = s1;
    }
    float s2 = scan_step4(m2, WA, eA, aA);
    if (h == 0) rtp[(TOUT - 1) * DV] = s2;
}

// ---------------- readout: GEMM + tanh + dot(p_W) + sigmoid ---------------
#define RT_ROWS 64
__global__ void __launch_bounds__(256)
readout_kernel(const float* __restrict__ p_W,
               const float* __restrict__ p_b,
               const int* __restrict__ skills,
               const int* __restrict__ responses,
               float* __restrict__ out,
               float* __restrict__ out2) {
    __shared__ __align__(16) float xs[RT_ROWS * DK];

    int tid  = threadIdx.x;
    int jg   = tid & 31;
    int rg   = tid >> 5;          // warp id 0..7
    int j0   = jg * 4;
    int row0 = blockIdx.x * RT_ROWS;

    // stage x tile (64x128 floats, coalesced float4)
    {
        const float4* src = reinterpret_cast<const float4*>(g_rt + row0 * DK);
        float4* dst = reinterpret_cast<float4*>(xs);
        #pragma unroll
        for (int u = 0; u < (RT_ROWS * DK / 4) / 256; u++)
            dst[tid + u * 256] = src[tid + u * 256];
    }

    // init accumulators with g_g gather (packed into lo half)
    u64 acc2[8][4];
    #pragma unroll
    for (int r = 0; r < 8; r++) {
        int gr = row0 + rg * 8 + r;
        int bb = gr / TOUT;
        int tt = gr - bb * TOUT;
        int sk = __ldg(skills + bb * T + tt);
        float4 g = __ldg(reinterpret_cast<const float4*>(g_g + sk * DK + j0));
        acc2[r][0] = pack2(g.x, 0.f);
        acc2[r][1] = pack2(g.y, 0.f);
        acc2[r][2] = pack2(g.z, 0.f);
        acc2[r][3] = pack2(g.w, 0.f);
    }
    __syncthreads();

    const float* xb = xs + rg * 8 * DK;

    #pragma unroll 4
    for (int ip = 0; ip < DK / 2; ip++) {
        const ulonglong2* wp =
            reinterpret_cast<const ulonglong2*>(g_fw2 + ip * DK + j0);
        ulonglong2 wv0 = __ldg(wp);
        ulonglong2 wv1 = __ldg(wp + 1);
        #pragma unroll
        for (int r = 0; r < 8; r++) {
            u64 x2 = *reinterpret_cast<const u64*>(xb + r * DK + 2 * ip);
            acc2[r][0] = fma2(x2, wv0.x, acc2[r][0]);
            acc2[r][1] = fma2(x2, wv0.y, acc2[r][1]);
            acc2[r][2] = fma2(x2, wv1.x, acc2[r][2]);
            acc2[r][3] = fma2(x2, wv1.y, acc2[r][3]);
        }
    }

    float4 pw = __ldg(reinterpret_cast<const float4*>(p_W + j0));
    float pb  = __ldg(p_b);
    #pragma unroll
    for (int r = 0; r < 8; r++) {
        float l0, h0, l1, h1, l2, h2, l3, h3;
        unpack2(acc2[r][0], l0, h0);
        unpack2(acc2[r][1], l1, h1);
        unpack2(acc2[r][2], l2, h2);
        unpack2(acc2[r][3], l3, h3);
        float s = tanhf(l0 + h0) * pw.x + tanhf(l1 + h1) * pw.y
                + tanhf(l2 + h2) * pw.z + tanhf(l3 + h3) * pw.w;
        #pragma unroll
        for (int off = 16; off; off >>= 1)
            s += __shfl_xor_sync(0xffffffffu, s, off);
        if (jg == 0) {
            int gr = row0 + rg * 8 + r;
            out[gr] = 1.0f / (1.0f + expf(-s));
        }
    }

    if (tid < RT_ROWS) {
        int gr = row0 + tid;
        int bb = gr / TOUT;
        int tt = gr - bb * TOUT;
        out2[gr] = (float)__ldg(responses + bb * T + tt + 1);
    }
}

// ---------------- launch ----------------------------------------------------
extern "C" void kernel_launch(void* const* d_in, const int* in_sizes, int n_in,
                              void* d_out, int out_size) {
    const int*   skills    = (const int*)  d_in[0];
    const int*   responses = (const int*)  d_in[1];
    const float* k_emb     = (const float*)d_in[2];
    const float* v_emb     = (const float*)d_in[3];
    const float* Mk        = (const float*)d_in[4];
    const float* Mv0       = (const float*)d_in[5];
    const float* f_W       = (const float*)d_in[6];
    const float* f_b       = (const float*)d_in[7];
    const float* p_W       = (const float*)d_in[8];
    const float* p_b       = (const float*)d_in[9];
    const float* e_W       = (const float*)d_in[10];
    const float* e_b       = (const float*)d_in[11];
    const float* a_W       = (const float*)d_in[12];
    const float* a_b       = (const float*)d_in[13];

    float* pred_out = (float*)d_out;
    float* true_out = pred_out + (out_size / 2);

    pre_wt_kernel<<<250, 128>>>(k_emb, Mk);
    pre_pack_kernel<<<32, 256>>>(f_W);
    pre_g_kernel<<<(NQ + PG_ROWS - 1) / PG_ROWS, 256>>>(k_emb, f_W, f_b);
    pre_ea_kernel<<<(2 * NQ) / EA_ROWS, 256>>>(v_emb, e_W, e_b, a_W, a_b);

    scan_kernel<<<B, 512>>>(skills, responses, Mv0);

    readout_kernel<<<NROWS / RT_ROWS, 256>>>(p_W, p_b, skills, responses,
                                             pred_out, true_out);
}

// round 4
// speedup vs baseline: 1.2383x; 1.2383x over previous
#include <cuda_runtime.h>
#include <cuda_bf16.h>

// Problem constants
#define B    256
#define T    256
#define NQ   1000
#define DK   128
#define DV   128
#define CC   32
#define TOUT 255
#define NROWS (B * TOUT)         // 65280

typedef unsigned long long u64;

// ---------------- packed f32x2 helpers (sm_103a) --------------------------
__device__ __forceinline__ u64 pack2(float lo, float hi) {
    u64 r; asm("mov.b64 %0, {%1, %2};" : "=l"(r) : "f"(lo), "f"(hi)); return r;
}
__device__ __forceinline__ void unpack2(u64 v, float& lo, float& hi) {
    asm("mov.b64 {%0, %1}, %2;" : "=f"(lo), "=f"(hi) : "l"(v));
}
__device__ __forceinline__ u64 fma2(u64 a, u64 b, u64 c) {
    u64 d; asm("fma.rn.f32x2 %0, %1, %2, %3;" : "=l"(d) : "l"(a), "l"(b), "l"(c)); return d;
}

// ---------------- device scratch ------------------------------------------
__device__ __align__(16) float g_wt[NQ * CC];        // softmax(k_emb @ Mk)
__device__ __align__(16) float g_g [NQ * DK];        // k_emb @ f_W[128:] + f_b
__device__ __align__(16) float g_et[2 * NQ * DV];    // sigmoid(v_emb @ e_W + e_b)
__device__ __align__(16) float g_at[2 * NQ * DV];    // tanh(v_emb @ a_W + a_b)
__device__ __align__(16) float g_rt[NROWS * DV];     // rt scratch
__device__ __align__(16) u64   g_fw2[(DK / 2) * DK]; // f_W rows 0..127, i-pair packed

// ---------------- fused precompute ------------------------------------------
// Block roles (256 threads each):
//   [0,250)    : pre_ea  (8 rows of v_emb each)
//   [250,375)  : pre_wt  (8 question rows each, one per warp)
//   [375,438)  : pre_g   (16 rows of k_emb each, clamped at 1000)
//   [438,470)  : pre_pack (256 entries of g_fw2 each)
#define EA_BLOCKS 250
#define WT_BLOCKS 125
#define PG_BLOCKS 63
#define PK_BLOCKS 32
#define PRE_BLOCKS (EA_BLOCKS + WT_BLOCKS + PG_BLOCKS + PK_BLOCKS)

__global__ void __launch_bounds__(256)
pre_fused_kernel(const float* __restrict__ k_emb,
                 const float* __restrict__ v_emb,
                 const float* __restrict__ Mk,
                 const float* __restrict__ f_W,
                 const float* __restrict__ f_b,
                 const float* __restrict__ e_W,
                 const float* __restrict__ e_b,
                 const float* __restrict__ a_W,
                 const float* __restrict__ a_b) {
    __shared__ __align__(16) float sbuf[16 * DK];    // 8KB, shared by roles
    int bid = blockIdx.x;
    int tid = threadIdx.x;

    if (bid < EA_BLOCKS) {
        // ---- pre_ea: et/at for 8 rows ----
        int row0 = bid * 8;
        int j  = tid & 127;
        int rh = tid >> 7;                            // 2 halves x 4 rows
        // stage 8x128 floats = 256 float4, one per thread
        reinterpret_cast<float4*>(sbuf)[tid] =
            __ldg(reinterpret_cast<const float4*>(v_emb + row0 * DV) + tid);
        __syncthreads();

        float acce[4], acca[4];
        float eb = __ldg(e_b + j), ab = __ldg(a_b + j);
        #pragma unroll
        for (int r = 0; r < 4; r++) { acce[r] = eb; acca[r] = ab; }

        const float* xb = sbuf + rh * 4 * DV;
        #pragma unroll 4
        for (int k = 0; k < DV; k += 4) {
            float we0 = __ldg(e_W + (k + 0) * DV + j);
            float we1 = __ldg(e_W + (k + 1) * DV + j);
            float we2 = __ldg(e_W + (k + 2) * DV + j);
            float we3 = __ldg(e_W + (k + 3) * DV + j);
            float wa0 = __ldg(a_W + (k + 0) * DV + j);
            float wa1 = __ldg(a_W + (k + 1) * DV + j);
            float wa2 = __ldg(a_W + (k + 2) * DV + j);
            float wa3 = __ldg(a_W + (k + 3) * DV + j);
            #pragma unroll
            for (int r = 0; r < 4; r++) {
                float4 xv = *reinterpret_cast<const float4*>(xb + r * DV + k);
                acce[r] = fmaf(xv.x, we0, acce[r]);
                acce[r] = fmaf(xv.y, we1, acce[r]);
                acce[r] = fmaf(xv.z, we2, acce[r]);
                acce[r] = fmaf(xv.w, we3, acce[r]);
                acca[r] = fmaf(xv.x, wa0, acca[r]);
                acca[r] = fmaf(xv.y, wa1, acca[r]);
                acca[r] = fmaf(xv.z, wa2, acca[r]);
                acca[r] = fmaf(xv.w, wa3, acca[r]);
            }
        }
        #pragma unroll
        for (int r = 0; r < 4; r++) {
            int gr = row0 + rh * 4 + r;
            g_et[gr * DV + j] = 1.0f / (1.0f + expf(-acce[r]));
            g_at[gr * DV + j] = tanhf(acca[r]);
        }
    } else if (bid < EA_BLOCKS + WT_BLOCKS) {
        // ---- pre_wt: softmax(k_emb @ Mk), one q per warp ----
        int warp = tid >> 5;
        int lane = tid & 31;
        int q = (bid - EA_BLOCKS) * 8 + warp;         // < 1000 exactly
        const float* krow = k_emb + q * DK;
        float acc = 0.f;
        #pragma unroll 8
        for (int k = 0; k < DK; k++)
            acc = fmaf(__ldg(krow + k), __ldg(Mk + k * CC + lane), acc);
        float mx = acc;
        #pragma unroll
        for (int off = 16; off; off >>= 1)
            mx = fmaxf(mx, __shfl_xor_sync(0xffffffffu, mx, off));
        float e = expf(acc - mx);
        float s = e;
        #pragma unroll
        for (int off = 16; off; off >>= 1)
            s += __shfl_xor_sync(0xffffffffu, s, off);
        g_wt[q * CC + lane] = e / s;
    } else if (bid < EA_BLOCKS + WT_BLOCKS + PG_BLOCKS) {
        // ---- pre_g: g = k_emb @ f_W[128:] + f_b, 16 rows ----
        int row0 = (bid - EA_BLOCKS - WT_BLOCKS) * 16;
        int j  = tid & 127;
        int rh = tid >> 7;                            // 2 halves x 8 rows
        #pragma unroll
        for (int u = 0; u < 2; u++) {
            int idx = tid + u * 256;                  // 512 float4 total
            int r   = idx >> 5;
            int gr  = row0 + r; if (gr >= NQ) gr = NQ - 1;
            reinterpret_cast<float4*>(sbuf)[idx] =
                __ldg(reinterpret_cast<const float4*>(k_emb + gr * DK) + (idx & 31));
        }
        __syncthreads();

        float acc[8];
        float fb = __ldg(f_b + j);
        #pragma unroll
        for (int r = 0; r < 8; r++) acc[r] = fb;

        const float* xb = sbuf + rh * 8 * DK;
        #pragma unroll 4
        for (int k = 0; k < DK; k += 4) {
            float w0 = __ldg(f_W + (DK + k + 0) * DK + j);
            float w1 = __ldg(f_W + (DK + k + 1) * DK + j);
            float w2 = __ldg(f_W + (DK + k + 2) * DK + j);
            float w3 = __ldg(f_W + (DK + k + 3) * DK + j);
            #pragma unroll
            for (int r = 0; r < 8; r++) {
                float4 xv = *reinterpret_cast<const float4*>(xb + r * DK + k);
                acc[r] = fmaf(xv.x, w0, acc[r]);
                acc[r] = fmaf(xv.y, w1, acc[r]);
                acc[r] = fmaf(xv.z, w2, acc[r]);
                acc[r] = fmaf(xv.w, w3, acc[r]);
            }
        }
        #pragma unroll
        for (int r = 0; r < 8; r++) {
            int gr = row0 + rh * 8 + r;
            if (gr < NQ) g_g[gr * DK + j] = acc[r];
        }
    } else {
        // ---- pre_pack: f_W lower half -> u64 i-pairs ----
        int idx = (bid - EA_BLOCKS - WT_BLOCKS - PG_BLOCKS) * 256 + tid;
        int ip = idx >> 7;
        int j  = idx & 127;
        g_fw2[idx] = pack2(__ldg(f_W + (2 * ip) * DK + j),
                           __ldg(f_W + (2 * ip + 1) * DK + j));
    }
}

// ---------------- sequential scan (round-2 shape: 128 thr, no shfl) --------
__device__ __forceinline__ void scan_load(int s, int q, int d,
                                          u64 W2[16], float& e, float& a) {
    const ulonglong2* wp = reinterpret_cast<const ulonglong2*>(g_wt + s * CC);
    #pragma unroll
    for (int u = 0; u < 8; u++) {
        ulonglong2 v = __ldg(wp + u);
        W2[2 * u]     = v.x;
        W2[2 * u + 1] = v.y;
    }
    e = __ldg(g_et + q * DV + d);
    a = __ldg(g_at + q * DV + d);
}

__device__ __forceinline__ float scan_step(u64 m2[16], const u64 W2[16],
                                           float e, float a) {
    u64 en2 = pack2(-e, -e);
    u64 a2  = pack2(a, a);
    u64 acc0 = 0ull, acc1 = 0ull;
    #pragma unroll
    for (int p = 0; p < 16; p++) {
        u64 mo = m2[p];
        if (p & 1) acc1 = fma2(W2[p], mo, acc1);
        else       acc0 = fma2(W2[p], mo, acc0);
        u64 tmp = fma2(mo, en2, a2);          // a - e*m
        m2[p] = fma2(W2[p], tmp, mo);         // m + w*(a - e*m)
    }
    float x0, x1, y0, y1;
    unpack2(acc0, x0, x1);
    unpack2(acc1, y0, y1);
    return (x0 + x1) + (y0 + y1);
}

__global__ void __launch_bounds__(128)
scan_kernel(const int* __restrict__ skills,
            const int* __restrict__ responses,
            const float* __restrict__ Mv0) {
    int b = blockIdx.x;
    int d = threadIdx.x;

    u64 m2[16];
    #pragma unroll
    for (int p = 0; p < 16; p++)
        m2[p] = pack2(__ldg(Mv0 + (2 * p) * DV + d),
                      __ldg(Mv0 + (2 * p + 1) * DV + d));

    const int* srow = skills + b * T;
    const int* rrow = responses + b * T;
    float* rtp = g_rt + (b * TOUT) * DV + d;

    int sn = __ldg(srow);
    int qn = sn + NQ * __ldg(rrow);
    u64 WA[16]; float eA, aA;
    scan_load(sn, qn, d, WA, eA, aA);
    sn = __ldg(srow + 1);
    qn = sn + NQ * __ldg(rrow + 1);

    for (int t = 0; t < TOUT - 1; t += 2) {
        u64 WB[16]; float eB, aB;
        scan_load(sn, qn, d, WB, eB, aB);
        sn = __ldg(srow + t + 2);
        qn = sn + NQ * __ldg(rrow + t + 2);

        rtp[t * DV] = scan_step(m2, WA, eA, aA);

        scan_load(sn, qn, d, WA, eA, aA);
        sn = __ldg(srow + t + 3);                 // t+3 <= 255, in range
        qn = sn + NQ * __ldg(rrow + t + 3);

        rtp[(t + 1) * DV] = scan_step(m2, WB, eB, aB);
    }
    rtp[(TOUT - 1) * DV] = scan_step(m2, WA, eA, aA);
}

// ---------------- readout: GEMM + tanh + dot(p_W) + sigmoid ---------------
#define RT_ROWS 64
__global__ void __launch_bounds__(256)
readout_kernel(const float* __restrict__ p_W,
               const float* __restrict__ p_b,
               const int* __restrict__ skills,
               const int* __restrict__ responses,
               float* __restrict__ out,
               float* __restrict__ out2) {
    __shared__ __align__(16) float xs[RT_ROWS * DK];

    int tid  = threadIdx.x;
    int jg   = tid & 31;
    int rg   = tid >> 5;          // warp id 0..7
    int j0   = jg * 4;
    int row0 = blockIdx.x * RT_ROWS;

    {
        const float4* src = reinterpret_cast<const float4*>(g_rt + row0 * DK);
        float4* dst = reinterpret_cast<float4*>(xs);
        #pragma unroll
        for (int u = 0; u < (RT_ROWS * DK / 4) / 256; u++)
            dst[tid + u * 256] = src[tid + u * 256];
    }

    u64 acc2[8][4];
    #pragma unroll
    for (int r = 0; r < 8; r++) {
        int gr = row0 + rg * 8 + r;
        int bb = gr / TOUT;
        int tt = gr - bb * TOUT;
        int sk = __ldg(skills + bb * T + tt);
        float4 g = __ldg(reinterpret_cast<const float4*>(g_g + sk * DK + j0));
        acc2[r][0] = pack2(g.x, 0.f);
        acc2[r][1] = pack2(g.y, 0.f);
        acc2[r][2] = pack2(g.z, 0.f);
        acc2[r][3] = pack2(g.w, 0.f);
    }
    __syncthreads();

    const float* xb = xs + rg * 8 * DK;

    #pragma unroll 4
    for (int ip = 0; ip < DK / 2; ip++) {
        const ulonglong2* wp =
            reinterpret_cast<const ulonglong2*>(g_fw2 + ip * DK + j0);
        ulonglong2 wv0 = __ldg(wp);
        ulonglong2 wv1 = __ldg(wp + 1);
        #pragma unroll
        for (int r = 0; r < 8; r++) {
            u64 x2 = *reinterpret_cast<const u64*>(xb + r * DK + 2 * ip);
            acc2[r][0] = fma2(x2, wv0.x, acc2[r][0]);
            acc2[r][1] = fma2(x2, wv0.y, acc2[r][1]);
            acc2[r][2] = fma2(x2, wv1.x, acc2[r][2]);
            acc2[r][3] = fma2(x2, wv1.y, acc2[r][3]);
        }
    }

    float4 pw = __ldg(reinterpret_cast<const float4*>(p_W + j0));
    float pb  = __ldg(p_b);
    #pragma unroll
    for (int r = 0; r < 8; r++) {
        float l0, h0, l1, h1, l2, h2, l3, h3;
        unpack2(acc2[r][0], l0, h0);
        unpack2(acc2[r][1], l1, h1);
        unpack2(acc2[r][2], l2, h2);
        unpack2(acc2[r][3], l3, h3);
        float s = tanhf(l0 + h0) * pw.x + tanhf(l1 + h1) * pw.y
                + tanhf(l2 + h2) * pw.z + tanhf(l3 + h3) * pw.w;
        #pragma unroll
        for (int off = 16; off; off >>= 1)
            s += __shfl_xor_sync(0xffffffffu, s, off);
        if (jg == 0) {
            int gr = row0 + rg * 8 + r;
            out[gr] = 1.0f / (1.0f + expf(-s));
        }
    }

    if (tid < RT_ROWS) {
        int gr = row0 + tid;
        int bb = gr / TOUT;
        int tt = gr - bb * TOUT;
        out2[gr] = (float)__ldg(responses + bb * T + tt + 1);
    }
}

// ---------------- launch ----------------------------------------------------
extern "C" void kernel_launch(void* const* d_in, const int* in_sizes, int n_in,
                              void* d_out, int out_size) {
    const int*   skills    = (const int*)  d_in[0];
    const int*   responses = (const int*)  d_in[1];
    const float* k_emb     = (const float*)d_in[2];
    const float* v_emb     = (const float*)d_in[3];
    const float* Mk        = (const float*)d_in[4];
    const float* Mv0       = (const float*)d_in[5];
    const float* f_W       = (const float*)d_in[6];
    const float* f_b       = (const float*)d_in[7];
    const float* p_W       = (const float*)d_in[8];
    const float* p_b       = (const float*)d_in[9];
    const float* e_W       = (const float*)d_in[10];
    const float* e_b       = (const float*)d_in[11];
    const float* a_W       = (const float*)d_in[12];
    const float* a_b       = (const float*)d_in[13];

    float* pred_out = (float*)d_out;
    float* true_out = pred_out + (out_size / 2);

    pre_fused_kernel<<<PRE_BLOCKS, 256>>>(k_emb, v_emb, Mk, f_W, f_b,
                                          e_W, e_b, a_W, a_b);

    scan_kernel<<<B, 128>>>(skills, responses, Mv0);

    readout_kernel<<<NROWS / RT_ROWS, 256>>>(p_W, p_b, skills, responses,
                                             pred_out, true_out);
}

// round 5
// speedup vs baseline: 1.2444x; 1.0050x over previous
#include <cuda_runtime.h>
#include <cuda_bf16.h>

// Problem constants
#define B    256
#define T    256
#define NQ   1000
#define DK   128
#define DV   128
#define CC   32
#define TOUT 255
#define NROWS (B * TOUT)         // 65280

typedef unsigned long long u64;

// ---------------- packed f32x2 helpers (sm_103a) --------------------------
__device__ __forceinline__ u64 pack2(float lo, float hi) {
    u64 r; asm("mov.b64 %0, {%1, %2};" : "=l"(r) : "f"(lo), "f"(hi)); return r;
}
__device__ __forceinline__ void unpack2(u64 v, float& lo, float& hi) {
    asm("mov.b64 {%0, %1}, %2;" : "=f"(lo), "=f"(hi) : "l"(v));
}
__device__ __forceinline__ u64 fma2(u64 a, u64 b, u64 c) {
    u64 d; asm("fma.rn.f32x2 %0, %1, %2, %3;" : "=l"(d) : "l"(a), "l"(b), "l"(c)); return d;
}

// ---------------- device scratch ------------------------------------------
__device__ __align__(16) float  g_wt[NQ * CC];        // softmax(k_emb @ Mk)
__device__ __align__(16) float  g_g [NQ * DK];        // k_emb @ f_W[128:] + f_b
__device__ __align__(16) float2 g_ea[2 * NQ * DV];    // (-sigmoid(vW_e), tanh(vW_a))
__device__ __align__(16) float  g_rt[NROWS * DV];     // rt scratch
__device__ __align__(16) u64    g_fw2[(DK / 2) * DK]; // f_W rows 0..127, i-pair packed

// ---------------- fused precompute ------------------------------------------
// Block roles (256 threads each):
//   [0,125)    : pre_ea  (16 rows of v_emb each)
//   [125,250)  : pre_wt  (8 question rows each, one per warp)
//   [250,313)  : pre_g   (16 rows of k_emb each, clamped at 1000)
//   [313,345)  : pre_pack (256 entries of g_fw2 each)
#define EA_BLOCKS 125
#define WT_BLOCKS 125
#define PG_BLOCKS 63
#define PK_BLOCKS 32
#define PRE_BLOCKS (EA_BLOCKS + WT_BLOCKS + PG_BLOCKS + PK_BLOCKS)

__global__ void __launch_bounds__(256)
pre_fused_kernel(const float* __restrict__ k_emb,
                 const float* __restrict__ v_emb,
                 const float* __restrict__ Mk,
                 const float* __restrict__ f_W,
                 const float* __restrict__ f_b,
                 const float* __restrict__ e_W,
                 const float* __restrict__ e_b,
                 const float* __restrict__ a_W,
                 const float* __restrict__ a_b) {
    __shared__ __align__(16) float sbuf[16 * DK];    // 8KB, shared by roles
    int bid = blockIdx.x;
    int tid = threadIdx.x;

    if (bid < EA_BLOCKS) {
        // ---- pre_ea: (-e, a) for 16 rows ----
        int row0 = bid * 16;
        int j  = tid & 127;
        int rh = tid >> 7;                            // 2 halves x 8 rows
        #pragma unroll
        for (int u = 0; u < 2; u++) {
            int idx = tid + u * 256;                  // 512 float4 total
            reinterpret_cast<float4*>(sbuf)[idx] =
                __ldg(reinterpret_cast<const float4*>(v_emb + row0 * DV) + idx);
        }
        __syncthreads();

        float acce[8], acca[8];
        float eb = __ldg(e_b + j), ab = __ldg(a_b + j);
        #pragma unroll
        for (int r = 0; r < 8; r++) { acce[r] = eb; acca[r] = ab; }

        const float* xb = sbuf + rh * 8 * DV;
        #pragma unroll 4
        for (int k = 0; k < DV; k += 4) {
            float we0 = __ldg(e_W + (k + 0) * DV + j);
            float we1 = __ldg(e_W + (k + 1) * DV + j);
            float we2 = __ldg(e_W + (k + 2) * DV + j);
            float we3 = __ldg(e_W + (k + 3) * DV + j);
            float wa0 = __ldg(a_W + (k + 0) * DV + j);
            float wa1 = __ldg(a_W + (k + 1) * DV + j);
            float wa2 = __ldg(a_W + (k + 2) * DV + j);
            float wa3 = __ldg(a_W + (k + 3) * DV + j);
            #pragma unroll
            for (int r = 0; r < 8; r++) {
                float4 xv = *reinterpret_cast<const float4*>(xb + r * DV + k);
                acce[r] = fmaf(xv.x, we0, acce[r]);
                acce[r] = fmaf(xv.y, we1, acce[r]);
                acce[r] = fmaf(xv.z, we2, acce[r]);
                acce[r] = fmaf(xv.w, we3, acce[r]);
                acca[r] = fmaf(xv.x, wa0, acca[r]);
                acca[r] = fmaf(xv.y, wa1, acca[r]);
                acca[r] = fmaf(xv.z, wa2, acca[r]);
                acca[r] = fmaf(xv.w, wa3, acca[r]);
            }
        }
        #pragma unroll
        for (int r = 0; r < 8; r++) {
            int gr = row0 + rh * 8 + r;
            g_ea[gr * DV + j] = make_float2(-1.0f / (1.0f + expf(-acce[r])),
                                            tanhf(acca[r]));
        }
    } else if (bid < EA_BLOCKS + WT_BLOCKS) {
        // ---- pre_wt: softmax(k_emb @ Mk), one q per warp ----
        int warp = tid >> 5;
        int lane = tid & 31;
        int q = (bid - EA_BLOCKS) * 8 + warp;         // < 1000 exactly
        const float* krow = k_emb + q * DK;
        float acc = 0.f;
        #pragma unroll 8
        for (int k = 0; k < DK; k++)
            acc = fmaf(__ldg(krow + k), __ldg(Mk + k * CC + lane), acc);
        float mx = acc;
        #pragma unroll
        for (int off = 16; off; off >>= 1)
            mx = fmaxf(mx, __shfl_xor_sync(0xffffffffu, mx, off));
        float e = expf(acc - mx);
        float s = e;
        #pragma unroll
        for (int off = 16; off; off >>= 1)
            s += __shfl_xor_sync(0xffffffffu, s, off);
        g_wt[q * CC + lane] = e / s;
    } else if (bid < EA_BLOCKS + WT_BLOCKS + PG_BLOCKS) {
        // ---- pre_g: g = k_emb @ f_W[128:] + f_b, 16 rows ----
        int row0 = (bid - EA_BLOCKS - WT_BLOCKS) * 16;
        int j  = tid & 127;
        int rh = tid >> 7;                            // 2 halves x 8 rows
        #pragma unroll
        for (int u = 0; u < 2; u++) {
            int idx = tid + u * 256;                  // 512 float4 total
            int r   = idx >> 5;
            int gr  = row0 + r; if (gr >= NQ) gr = NQ - 1;
            reinterpret_cast<float4*>(sbuf)[idx] =
                __ldg(reinterpret_cast<const float4*>(k_emb + gr * DK) + (idx & 31));
        }
        __syncthreads();

        float acc[8];
        float fb = __ldg(f_b + j);
        #pragma unroll
        for (int r = 0; r < 8; r++) acc[r] = fb;

        const float* xb = sbuf + rh * 8 * DK;
        #pragma unroll 4
        for (int k = 0; k < DK; k += 4) {
            float w0 = __ldg(f_W + (DK + k + 0) * DK + j);
            float w1 = __ldg(f_W + (DK + k + 1) * DK + j);
            float w2 = __ldg(f_W + (DK + k + 2) * DK + j);
            float w3 = __ldg(f_W + (DK + k + 3) * DK + j);
            #pragma unroll
            for (int r = 0; r < 8; r++) {
                float4 xv = *reinterpret_cast<const float4*>(xb + r * DK + k);
                acc[r] = fmaf(xv.x, w0, acc[r]);
                acc[r] = fmaf(xv.y, w1, acc[r]);
                acc[r] = fmaf(xv.z, w2, acc[r]);
                acc[r] = fmaf(xv.w, w3, acc[r]);
            }
        }
        #pragma unroll
        for (int r = 0; r < 8; r++) {
            int gr = row0 + rh * 8 + r;
            if (gr < NQ) g_g[gr * DK + j] = acc[r];
        }
    } else {
        // ---- pre_pack: f_W lower half -> u64 i-pairs ----
        int idx = (bid - EA_BLOCKS - WT_BLOCKS - PG_BLOCKS) * 256 + tid;
        int ip = idx >> 7;
        int j  = idx & 127;
        g_fw2[idx] = pack2(__ldg(f_W + (2 * ip) * DK + j),
                           __ldg(f_W + (2 * ip + 1) * DK + j));
    }
}

// ---------------- sequential scan: 2 d-columns per thread ------------------
// Block = 128 threads: warps 0-1 handle batch 2*bid, warps 2-3 batch 2*bid+1.
// Thread td in [0,64) owns d0=td and d1=td+64 -> W row loaded ONCE per step
// serves both columns. e/a fetched as a single float2 (e pre-negated).

__device__ __forceinline__ void scan_loadW(int s, u64 W2[16]) {
    const ulonglong2* wp = reinterpret_cast<const ulonglong2*>(g_wt + s * CC);
    #pragma unroll
    for (int u = 0; u < 8; u++) {
        ulonglong2 v = __ldg(wp + u);
        W2[2 * u]     = v.x;
        W2[2 * u + 1] = v.y;
    }
}

__device__ __forceinline__ float scan_step(u64 m2[16], const u64 W2[16],
                                           float ne, float a) {
    u64 en2 = pack2(ne, ne);
    u64 a2  = pack2(a, a);
    u64 acc0 = 0ull, acc1 = 0ull;
    #pragma unroll
    for (int p = 0; p < 16; p++) {
        u64 mo = m2[p];
        if (p & 1) acc1 = fma2(W2[p], mo, acc1);
        else       acc0 = fma2(W2[p], mo, acc0);
        u64 tmp = fma2(mo, en2, a2);          // a - e*m
        m2[p] = fma2(W2[p], tmp, mo);         // m + w*(a - e*m)
    }
    float x0, x1, y0, y1;
    unpack2(acc0, x0, x1);
    unpack2(acc1, y0, y1);
    return (x0 + x1) + (y0 + y1);
}

__global__ void __launch_bounds__(128, 1)
scan_kernel(const int* __restrict__ skills,
            const int* __restrict__ responses,
            const float* __restrict__ Mv0) {
    int tid  = threadIdx.x;
    int half = tid >> 6;                 // 0/1 -> batch within block
    int td   = tid & 63;
    int b    = blockIdx.x * 2 + half;
    int d0   = td;
    int d1   = td + 64;

    u64 m0[16], m1[16];
    #pragma unroll
    for (int p = 0; p < 16; p++) {
        m0[p] = pack2(__ldg(Mv0 + (2 * p) * DV + d0),
                      __ldg(Mv0 + (2 * p + 1) * DV + d0));
        m1[p] = pack2(__ldg(Mv0 + (2 * p) * DV + d1),
                      __ldg(Mv0 + (2 * p + 1) * DV + d1));
    }

    const int* srow = skills + b * T;
    const int* rrow = responses + b * T;
    float* rtp0 = g_rt + (b * TOUT) * DV + d0;
    float* rtp1 = g_rt + (b * TOUT) * DV + d1;

    // data for step 0
    int sn = __ldg(srow);
    int qn = sn + NQ * __ldg(rrow);
    u64 WA[16]; float2 eaA0, eaA1;
    scan_loadW(sn, WA);
    eaA0 = __ldg(g_ea + qn * DV + d0);
    eaA1 = __ldg(g_ea + qn * DV + d1);
    // indices for step 1
    sn = __ldg(srow + 1);
    qn = sn + NQ * __ldg(rrow + 1);

    for (int t = 0; t < TOUT - 1; t += 2) {
        // prefetch data for t+1
        u64 WB[16]; float2 eaB0, eaB1;
        scan_loadW(sn, WB);
        eaB0 = __ldg(g_ea + qn * DV + d0);
        eaB1 = __ldg(g_ea + qn * DV + d1);
        sn = __ldg(srow + t + 2);
        qn = sn + NQ * __ldg(rrow + t + 2);

        rtp0[t * DV] = scan_step(m0, WA, eaA0.x, eaA0.y);
        rtp1[t * DV] = scan_step(m1, WA, eaA1.x, eaA1.y);

        // prefetch data for t+2
        scan_loadW(sn, WA);
        eaA0 = __ldg(g_ea + qn * DV + d0);
        eaA1 = __ldg(g_ea + qn * DV + d1);
        sn = __ldg(srow + t + 3);                 // t+3 <= 255, in range
        qn = sn + NQ * __ldg(rrow + t + 3);

        rtp0[(t + 1) * DV] = scan_step(m0, WB, eaB0.x, eaB0.y);
        rtp1[(t + 1) * DV] = scan_step(m1, WB, eaB1.x, eaB1.y);
    }
    rtp0[(TOUT - 1) * DV] = scan_step(m0, WA, eaA0.x, eaA0.y);
    rtp1[(TOUT - 1) * DV] = scan_step(m1, WA, eaA1.x, eaA1.y);
}

// ---------------- readout: GEMM + tanh + dot(p_W) + sigmoid ---------------
#define RT_ROWS 64
__global__ void __launch_bounds__(256)
readout_kernel(const float* __restrict__ p_W,
               const float* __restrict__ p_b,
               const int* __restrict__ skills,
               const int* __restrict__ responses,
               float* __restrict__ out,
               float* __restrict__ out2) {
    __shared__ __align__(16) float xs[RT_ROWS * DK];

    int tid  = threadIdx.x;
    int jg   = tid & 31;
    int rg   = tid >> 5;          // warp id 0..7
    int j0   = jg * 4;
    int row0 = blockIdx.x * RT_ROWS;

    {
        const float4* src = reinterpret_cast<const float4*>(g_rt + row0 * DK);
        float4* dst = reinterpret_cast<float4*>(xs);
        #pragma unroll
        for (int u = 0; u < (RT_ROWS * DK / 4) / 256; u++)
            dst[tid + u * 256] = src[tid + u * 256];
    }

    u64 acc2[8][4];
    #pragma unroll
    for (int r = 0; r < 8; r++) {
        int gr = row0 + rg * 8 + r;
        int bb = gr / TOUT;
        int tt = gr - bb * TOUT;
        int sk = __ldg(skills + bb * T + tt);
        float4 g = __ldg(reinterpret_cast<const float4*>(g_g + sk * DK + j0));
        acc2[r][0] = pack2(g.x, 0.f);
        acc2[r][1] = pack2(g.y, 0.f);
        acc2[r][2] = pack2(g.z, 0.f);
        acc2[r][3] = pack2(g.w, 0.f);
    }
    __syncthreads();

    const float* xb = xs + rg * 8 * DK;

    #pragma unroll 4
    for (int ip = 0; ip < DK / 2; ip++) {
        const ulonglong2* wp =
            reinterpret_cast<const ulonglong2*>(g_fw2 + ip * DK + j0);
        ulonglong2 wv0 = __ldg(wp);
        ulonglong2 wv1 = __ldg(wp + 1);
        #pragma unroll
        for (int r = 0; r < 8; r++) {
            u64 x2 = *reinterpret_cast<const u64*>(xb + r * DK + 2 * ip);
            acc2[r][0] = fma2(x2, wv0.x, acc2[r][0]);
            acc2[r][1] = fma2(x2, wv0.y, acc2[r][1]);
            acc2[r][2] = fma2(x2, wv1.x, acc2[r][2]);
            acc2[r][3] = fma2(x2, wv1.y, acc2[r][3]);
        }
    }

    float4 pw = __ldg(reinterpret_cast<const float4*>(p_W + j0));
    float pb  = __ldg(p_b);
    #pragma unroll
    for (int r = 0; r < 8; r++) {
        float l0, h0, l1, h1, l2, h2, l3, h3;
        unpack2(acc2[r][0], l0, h0);
        unpack2(acc2[r][1], l1, h1);
        unpack2(acc2[r][2], l2, h2);
        unpack2(acc2[r][3], l3, h3);
        float s = tanhf(l0 + h0) * pw.x + tanhf(l1 + h1) * pw.y
                + tanhf(l2 + h2) * pw.z + tanhf(l3 + h3) * pw.w;
        #pragma unroll
        for (int off = 16; off; off >>= 1)
            s += __shfl_xor_sync(0xffffffffu, s, off);
        if (jg == 0) {
            int gr = row0 + rg * 8 + r;
            out[gr] = 1.0f / (1.0f + expf(-s));
        }
    }

    if (tid < RT_ROWS) {
        int gr = row0 + tid;
        int bb = gr / TOUT;
        int tt = gr - bb * TOUT;
        out2[gr] = (float)__ldg(responses + bb * T + tt + 1);
    }
}

// ---------------- launch ----------------------------------------------------
extern "C" void kernel_launch(void* const* d_in, const int* in_sizes, int n_in,
                              void* d_out, int out_size) {
    const int*   skills    = (const int*)  d_in[0];
    const int*   responses = (const int*)  d_in[1];
    const float* k_emb     = (const float*)d_in[2];
    const float* v_emb     = (const float*)d_in[3];
    const float* Mk        = (const float*)d_in[4];
    const float* Mv0       = (const float*)d_in[5];
    const float* f_W       = (const float*)d_in[6];
    const float* f_b       = (const float*)d_in[7];
    const float* p_W       = (const float*)d_in[8];
    const float* p_b       = (const float*)d_in[9];
    const float* e_W       = (const float*)d_in[10];
    const float* e_b       = (const float*)d_in[11];
    const float* a_W       = (const float*)d_in[12];
    const float* a_b       = (const float*)d_in[13];

    float* pred_out = (float*)d_out;
    float* true_out = pred_out + (out_size / 2);

    pre_fused_kernel<<<PRE_BLOCKS, 256>>>(k_emb, v_emb, Mk, f_W, f_b,
                                          e_W, e_b, a_W, a_b);

    scan_kernel<<<B / 2, 128>>>(skills, responses, Mv0);

    readout_kernel<<<NROWS / RT_ROWS, 256>>>(p_W, p_b, skills, responses,
                                             pred_out, true_out);
}

// round 6
// speedup vs baseline: 1.2510x; 1.0052x over previous
#include <cuda_runtime.h>
#include <cuda_bf16.h>

// Problem constants
#define B    256
#define T    256
#define NQ   1000
#define DK   128
#define DV   128
#define CC   32
#define TOUT 255
#define NROWS (B * TOUT)         // 65280

typedef unsigned long long u64;

// ---------------- packed f32x2 helpers (sm_103a) --------------------------
__device__ __forceinline__ u64 pack2(float lo, float hi) {
    u64 r; asm("mov.b64 %0, {%1, %2};" : "=l"(r) : "f"(lo), "f"(hi)); return r;
}
__device__ __forceinline__ void unpack2(u64 v, float& lo, float& hi) {
    asm("mov.b64 {%0, %1}, %2;" : "=f"(lo), "=f"(hi) : "l"(v));
}
__device__ __forceinline__ u64 fma2(u64 a, u64 b, u64 c) {
    u64 d; asm("fma.rn.f32x2 %0, %1, %2, %3;" : "=l"(d) : "l"(a), "l"(b), "l"(c)); return d;
}

// ---------------- device scratch ------------------------------------------
__device__ __align__(16) float  g_wt[NQ * CC];        // softmax(k_emb @ Mk)
__device__ __align__(16) float  g_g [NQ * DK];        // k_emb @ f_W[128:] + f_b
__device__ __align__(16) float2 g_ea[2 * NQ * DV];    // (-sigmoid(vW_e), tanh(vW_a))
__device__ __align__(16) float  g_rt[NROWS * DV];     // rt scratch
__device__ __align__(16) u64    g_fw2[(DK / 2) * DK]; // f_W rows 0..127, i-pair packed

// ---------------- fused precompute ------------------------------------------
#define EA_BLOCKS 125
#define WT_BLOCKS 125
#define PG_BLOCKS 63
#define PK_BLOCKS 32
#define PRE_BLOCKS (EA_BLOCKS + WT_BLOCKS + PG_BLOCKS + PK_BLOCKS)

__global__ void __launch_bounds__(256)
pre_fused_kernel(const float* __restrict__ k_emb,
                 const float* __restrict__ v_emb,
                 const float* __restrict__ Mk,
                 const float* __restrict__ f_W,
                 const float* __restrict__ f_b,
                 const float* __restrict__ e_W,
                 const float* __restrict__ e_b,
                 const float* __restrict__ a_W,
                 const float* __restrict__ a_b) {
    __shared__ __align__(16) float sbuf[16 * DK];    // 8KB, shared by roles
    int bid = blockIdx.x;
    int tid = threadIdx.x;

    if (bid < EA_BLOCKS) {
        // ---- pre_ea: (-e, a) for 16 rows, f32x2 over k-pairs ----
        int row0 = bid * 16;
        int j  = tid & 127;
        int rh = tid >> 7;                            // 2 halves x 8 rows
        #pragma unroll
        for (int u = 0; u < 2; u++) {
            int idx = tid + u * 256;                  // 512 float4 total
            reinterpret_cast<float4*>(sbuf)[idx] =
                __ldg(reinterpret_cast<const float4*>(v_emb + row0 * DV) + idx);
        }
        __syncthreads();

        u64 acce[8], acca[8];
        float eb = __ldg(e_b + j), ab = __ldg(a_b + j);
        #pragma unroll
        for (int r = 0; r < 8; r++) {
            acce[r] = pack2(eb, 0.f);
            acca[r] = pack2(ab, 0.f);
        }

        const float* xb = sbuf + rh * 8 * DV;
        #pragma unroll 4
        for (int k = 0; k < DV; k += 2) {
            u64 we = pack2(__ldg(e_W + k * DV + j), __ldg(e_W + (k + 1) * DV + j));
            u64 wa = pack2(__ldg(a_W + k * DV + j), __ldg(a_W + (k + 1) * DV + j));
            #pragma unroll
            for (int r = 0; r < 8; r++) {
                u64 x2 = *reinterpret_cast<const u64*>(xb + r * DV + k);
                acce[r] = fma2(x2, we, acce[r]);
                acca[r] = fma2(x2, wa, acca[r]);
            }
        }
        #pragma unroll
        for (int r = 0; r < 8; r++) {
            int gr = row0 + rh * 8 + r;
            float el, eh, al, ah;
            unpack2(acce[r], el, eh);
            unpack2(acca[r], al, ah);
            g_ea[gr * DV + j] = make_float2(-1.0f / (1.0f + expf(-(el + eh))),
                                            tanhf(al + ah));
        }
    } else if (bid < EA_BLOCKS + WT_BLOCKS) {
        // ---- pre_wt: softmax(k_emb @ Mk), one q per warp ----
        int warp = tid >> 5;
        int lane = tid & 31;
        int q = (bid - EA_BLOCKS) * 8 + warp;         // < 1000 exactly
        const float4* krow = reinterpret_cast<const float4*>(k_emb + q * DK);
        float acc = 0.f;
        #pragma unroll 8
        for (int k4 = 0; k4 < DK / 4; k4++) {
            float4 kv = __ldg(krow + k4);
            acc = fmaf(kv.x, __ldg(Mk + (4 * k4 + 0) * CC + lane), acc);
            acc = fmaf(kv.y, __ldg(Mk + (4 * k4 + 1) * CC + lane), acc);
            acc = fmaf(kv.z, __ldg(Mk + (4 * k4 + 2) * CC + lane), acc);
            acc = fmaf(kv.w, __ldg(Mk + (4 * k4 + 3) * CC + lane), acc);
        }
        float mx = acc;
        #pragma unroll
        for (int off = 16; off; off >>= 1)
            mx = fmaxf(mx, __shfl_xor_sync(0xffffffffu, mx, off));
        float e = expf(acc - mx);
        float s = e;
        #pragma unroll
        for (int off = 16; off; off >>= 1)
            s += __shfl_xor_sync(0xffffffffu, s, off);
        g_wt[q * CC + lane] = e / s;
    } else if (bid < EA_BLOCKS + WT_BLOCKS + PG_BLOCKS) {
        // ---- pre_g: g = k_emb @ f_W[128:] + f_b, 16 rows ----
        int row0 = (bid - EA_BLOCKS - WT_BLOCKS) * 16;
        int j  = tid & 127;
        int rh = tid >> 7;                            // 2 halves x 8 rows
        #pragma unroll
        for (int u = 0; u < 2; u++) {
            int idx = tid + u * 256;                  // 512 float4 total
            int r   = idx >> 5;
            int gr  = row0 + r; if (gr >= NQ) gr = NQ - 1;
            reinterpret_cast<float4*>(sbuf)[idx] =
                __ldg(reinterpret_cast<const float4*>(k_emb + gr * DK) + (idx & 31));
        }
        __syncthreads();

        u64 acc[8];
        float fb = __ldg(f_b + j);
        #pragma unroll
        for (int r = 0; r < 8; r++) acc[r] = pack2(fb, 0.f);

        const float* xb = sbuf + rh * 8 * DK;
        #pragma unroll 4
        for (int k = 0; k < DK; k += 2) {
            u64 w = pack2(__ldg(f_W + (DK + k) * DK + j),
                          __ldg(f_W + (DK + k + 1) * DK + j));
            #pragma unroll
            for (int r = 0; r < 8; r++) {
                u64 x2 = *reinterpret_cast<const u64*>(xb + r * DK + k);
                acc[r] = fma2(x2, w, acc[r]);
            }
        }
        #pragma unroll
        for (int r = 0; r < 8; r++) {
            int gr = row0 + rh * 8 + r;
            float lo, hi;
            unpack2(acc[r], lo, hi);
            if (gr < NQ) g_g[gr * DK + j] = lo + hi;
        }
    } else {
        // ---- pre_pack: f_W lower half -> u64 i-pairs ----
        int idx = (bid - EA_BLOCKS - WT_BLOCKS - PG_BLOCKS) * 256 + tid;
        int ip = idx >> 7;
        int j  = idx & 127;
        g_fw2[idx] = pack2(__ldg(f_W + (2 * ip) * DK + j),
                           __ldg(f_W + (2 * ip + 1) * DK + j));
    }
}

// ---------------- sequential scan: 2 d-cols/thread, unroll-4 pipeline ------
// Block = 128 threads: warps 0-1 handle batch 2*bid, warps 2-3 batch 2*bid+1.
// Thread td in [0,64) owns d0=td and d1=td+64. W loaded once per step for
// both columns (L1-resident g_wt, depth-1 prefetch). g_ea (L2-resident, 2MB)
// prefetched 4-7 steps ahead to cover ~250cyc L2 latency.

__device__ __forceinline__ void scan_loadW(int s, u64 W2[16]) {
    const ulonglong2* wp = reinterpret_cast<const ulonglong2*>(g_wt + s * CC);
    #pragma unroll
    for (int u = 0; u < 8; u++) {
        ulonglong2 v = __ldg(wp + u);
        W2[2 * u]     = v.x;
        W2[2 * u + 1] = v.y;
    }
}

__device__ __forceinline__ float scan_step(u64 m2[16], const u64 W2[16],
                                           float ne, float a) {
    u64 en2 = pack2(ne, ne);
    u64 a2  = pack2(a, a);
    u64 acc0 = 0ull, acc1 = 0ull;
    #pragma unroll
    for (int p = 0; p < 16; p++) {
        u64 mo = m2[p];
        if (p & 1) acc1 = fma2(W2[p], mo, acc1);
        else       acc0 = fma2(W2[p], mo, acc0);
        u64 tmp = fma2(mo, en2, a2);          // a - e*m
        m2[p] = fma2(W2[p], tmp, mo);         // m + w*(a - e*m)
    }
    float x0, x1, y0, y1;
    unpack2(acc0, x0, x1);
    unpack2(acc1, y0, y1);
    return (x0 + x1) + (y0 + y1);
}

__global__ void __launch_bounds__(128, 1)
scan_kernel(const int* __restrict__ skills,
            const int* __restrict__ responses,
            const float* __restrict__ Mv0) {
    int tid  = threadIdx.x;
    int half = tid >> 6;                 // 0/1 -> batch within block
    int td   = tid & 63;
    int b    = blockIdx.x * 2 + half;
    int d0   = td;
    int d1   = td + 64;

    u64 m0[16], m1[16];
    #pragma unroll
    for (int p = 0; p < 16; p++) {
        m0[p] = pack2(__ldg(Mv0 + (2 * p) * DV + d0),
                      __ldg(Mv0 + (2 * p + 1) * DV + d0));
        m1[p] = pack2(__ldg(Mv0 + (2 * p) * DV + d1),
                      __ldg(Mv0 + (2 * p + 1) * DV + d1));
    }

    const int* srow = skills + b * T;
    const int* rrow = responses + b * T;
    float* rtp0 = g_rt + (b * TOUT) * DV + d0;
    float* rtp1 = g_rt + (b * TOUT) * DV + d1;

    // staging for steps t..t+3
    int  s4[4];
    float2 E0[4], E1[4];
    #pragma unroll
    for (int k = 0; k < 4; k++) {
        int s = __ldg(srow + k);
        int q = s + NQ * __ldg(rrow + k);
        s4[k] = s;
        E0[k] = __ldg(g_ea + q * DV + d0);
        E1[k] = __ldg(g_ea + q * DV + d1);
    }
    u64 W0[16];
    scan_loadW(s4[0], W0);

    // main loop: t = 0,4,8,...,248  (63 bodies, steps 0..251)
    for (int t = 0; t < TOUT - 3; t += 4) {
        u64 W1[16], W2[16], W3[16];
        // staging for t+4..t+7 (t+7 <= 255, in range)
        int    ns[4];
        float2 nE0[4], nE1[4];

        scan_loadW(s4[1], W1);
        rtp0[t * DV] = scan_step(m0, W0, E0[0].x, E0[0].y);
        rtp1[t * DV] = scan_step(m1, W0, E1[0].x, E1[0].y);

        scan_loadW(s4[2], W2);
        #pragma unroll
        for (int k = 0; k < 4; k++) {
            int s = __ldg(srow + t + 4 + k);
            int q = s + NQ * __ldg(rrow + t + 4 + k);
            ns[k]  = s;
            nE0[k] = __ldg(g_ea + q * DV + d0);
            nE1[k] = __ldg(g_ea + q * DV + d1);
        }
        rtp0[(t + 1) * DV] = scan_step(m0, W1, E0[1].x, E0[1].y);
        rtp1[(t + 1) * DV] = scan_step(m1, W1, E1[1].x, E1[1].y);

        scan_loadW(s4[3], W3);
        rtp0[(t + 2) * DV] = scan_step(m0, W2, E0[2].x, E0[2].y);
        rtp1[(t + 2) * DV] = scan_step(m1, W2, E1[2].x, E1[2].y);

        scan_loadW(ns[0], W0);              // W for t+4
        rtp0[(t + 3) * DV] = scan_step(m0, W3, E0[3].x, E0[3].y);
        rtp1[(t + 3) * DV] = scan_step(m1, W3, E1[3].x, E1[3].y);

        #pragma unroll
        for (int k = 0; k < 4; k++) {
            s4[k] = ns[k];
            E0[k] = nE0[k];
            E1[k] = nE1[k];
        }
    }

    // tail: steps 252, 253, 254 (data staged; s4/E hold 252..255)
    {
        u64 W1[16], W2[16];
        scan_loadW(s4[1], W1);
        rtp0[252 * DV] = scan_step(m0, W0, E0[0].x, E0[0].y);
        rtp1[252 * DV] = scan_step(m1, W0, E1[0].x, E1[0].y);
        scan_loadW(s4[2], W2);
        rtp0[253 * DV] = scan_step(m0, W1, E0[1].x, E0[1].y);
        rtp1[253 * DV] = scan_step(m1, W1, E1[1].x, E1[1].y);
        rtp0[254 * DV] = scan_step(m0, W2, E0[2].x, E0[2].y);
        rtp1[254 * DV] = scan_step(m1, W2, E1[2].x, E1[2].y);
    }
}

// ---------------- readout: GEMM + tanh + dot(p_W) + sigmoid ---------------
#define RT_ROWS 64
__global__ void __launch_bounds__(256)
readout_kernel(const float* __restrict__ p_W,
               const float* __restrict__ p_b,
               const int* __restrict__ skills,
               const int* __restrict__ responses,
               float* __restrict__ out,
               float* __restrict__ out2) {
    __shared__ __align__(16) float xs[RT_ROWS * DK];

    int tid  = threadIdx.x;
    int jg   = tid & 31;
    int rg   = tid >> 5;          // warp id 0..7
    int j0   = jg * 4;
    int row0 = blockIdx.x * RT_ROWS;

    {
        const float4* src = reinterpret_cast<const float4*>(g_rt + row0 * DK);
        float4* dst = reinterpret_cast<float4*>(xs);
        #pragma unroll
        for (int u = 0; u < (RT_ROWS * DK / 4) / 256; u++)
            dst[tid + u * 256] = src[tid + u * 256];
    }

    u64 acc2[8][4];
    #pragma unroll
    for (int r = 0; r < 8; r++) {
        int gr = row0 + rg * 8 + r;
        int bb = gr / TOUT;
        int tt = gr - bb * TOUT;
        int sk = __ldg(skills + bb * T + tt);
        float4 g = __ldg(reinterpret_cast<const float4*>(g_g + sk * DK + j0));
        acc2[r][0] = pack2(g.x, 0.f);
        acc2[r][1] = pack2(g.y, 0.f);
        acc2[r][2] = pack2(g.z, 0.f);
        acc2[r][3] = pack2(g.w, 0.f);
    }
    __syncthreads();

    const float* xb = xs + rg * 8 * DK;

    #pragma unroll 4
    for (int ip = 0; ip < DK / 2; ip++) {
        const ulonglong2* wp =
            reinterpret_cast<const ulonglong2*>(g_fw2 + ip * DK + j0);
        ulonglong2 wv0 = __ldg(wp);
        ulonglong2 wv1 = __ldg(wp + 1);
        #pragma unroll
        for (int r = 0; r < 8; r++) {
            u64 x2 = *reinterpret_cast<const u64*>(xb + r * DK + 2 * ip);
            acc2[r][0] = fma2(x2, wv0.x, acc2[r][0]);
            acc2[r][1] = fma2(x2, wv0.y, acc2[r][1]);
            acc2[r][2] = fma2(x2, wv1.x, acc2[r][2]);
            acc2[r][3] = fma2(x2, wv1.y, acc2[r][3]);
        }
    }

    float4 pw = __ldg(reinterpret_cast<const float4*>(p_W + j0));
    float pb  = __ldg(p_b);
    #pragma unroll
    for (int r = 0; r < 8; r++) {
        float l0, h0, l1, h1, l2, h2, l3, h3;
        unpack2(acc2[r][0], l0, h0);
        unpack2(acc2[r][1], l1, h1);
        unpack2(acc2[r][2], l2, h2);
        unpack2(acc2[r][3], l3, h3);
        float s = tanhf(l0 + h0) * pw.x + tanhf(l1 + h1) * pw.y
                + tanhf(l2 + h2) * pw.z + tanhf(l3 + h3) * pw.w;
        #pragma unroll
        for (int off = 16; off; off >>= 1)
            s += __shfl_xor_sync(0xffffffffu, s, off);
        if (jg == 0) {
            int gr = row0 + rg * 8 + r;
            out[gr] = 1.0f / (1.0f + expf(-s));
        }
    }

    if (tid < RT_ROWS) {
        int gr = row0 + tid;
        int bb = gr / TOUT;
        int tt = gr - bb * TOUT;
        out2[gr] = (float)__ldg(responses + bb * T + tt + 1);
    }
}

// ---------------- launch ----------------------------------------------------
extern "C" void kernel_launch(void* const* d_in, const int* in_sizes, int n_in,
                              void* d_out, int out_size) {
    const int*   skills    = (const int*)  d_in[0];
    const int*   responses = (const int*)  d_in[1];
    const float* k_emb     = (const float*)d_in[2];
    const float* v_emb     = (const float*)d_in[3];
    const float* Mk        = (const float*)d_in[4];
    const float* Mv0       = (const float*)d_in[5];
    const float* f_W       = (const float*)d_in[6];
    const float* f_b       = (const float*)d_in[7];
    const float* p_W       = (const float*)d_in[8];
    const float* p_b       = (const float*)d_in[9];
    const float* e_W       = (const float*)d_in[10];
    const float* e_b       = (const float*)d_in[11];
    const float* a_W       = (const float*)d_in[12];
    const float* a_b       = (const float*)d_in[13];

    float* pred_out = (float*)d_out;
    float* true_out = pred_out + (out_size / 2);

    pre_fused_kernel<<<PRE_BLOCKS, 256>>>(k_emb, v_emb, Mk, f_W, f_b,
                                          e_W, e_b, a_W, a_b);

    scan_kernel<<<B / 2, 128>>>(skills, responses, Mv0);

    readout_kernel<<<NROWS / RT_ROWS, 256>>>(p_W, p_b, skills, responses,
                                             pred_out, true_out);
}

// round 7
// speedup vs baseline: 1.2861x; 1.0281x over previous
#include <cuda_runtime.h>
#include <cuda_bf16.h>

// Problem constants
#define B    256
#define T    256
#define NQ   1000
#define DK   128
#define DV   128
#define CC   32
#define TOUT 255
#define NROWS (B * TOUT)         // 65280

typedef unsigned long long u64;

// ---------------- packed f32x2 helpers (sm_103a) --------------------------
__device__ __forceinline__ u64 pack2(float lo, float hi) {
    u64 r; asm("mov.b64 %0, {%1, %2};" : "=l"(r) : "f"(lo), "f"(hi)); return r;
}
__device__ __forceinline__ void unpack2(u64 v, float& lo, float& hi) {
    asm("mov.b64 {%0, %1}, %2;" : "=f"(lo), "=f"(hi) : "l"(v));
}
__device__ __forceinline__ u64 fma2(u64 a, u64 b, u64 c) {
    u64 d; asm("fma.rn.f32x2 %0, %1, %2, %3;" : "=l"(d) : "l"(a), "l"(b), "l"(c)); return d;
}

// ---------------- device scratch ------------------------------------------
__device__ __align__(16) float  g_wt[NQ * CC];        // softmax(k_emb @ Mk)
__device__ __align__(16) float  g_g [NQ * DK];        // k_emb @ f_W[128:] + f_b
__device__ __align__(16) float2 g_ea[2 * NQ * DV];    // (-sigmoid(vW_e), tanh(vW_a))
__device__ __align__(16) float  g_rt[NROWS * DV];     // rt scratch
__device__ __align__(16) u64    g_fw2[(DK / 2) * DK]; // f_W rows 0..127, i-pair packed

// ---------------- fused precompute (round-5 version, measured 20.9us) ------
#define EA_BLOCKS 125
#define WT_BLOCKS 125
#define PG_BLOCKS 63
#define PK_BLOCKS 32
#define PRE_BLOCKS (EA_BLOCKS + WT_BLOCKS + PG_BLOCKS + PK_BLOCKS)

__global__ void __launch_bounds__(256)
pre_fused_kernel(const float* __restrict__ k_emb,
                 const float* __restrict__ v_emb,
                 const float* __restrict__ Mk,
                 const float* __restrict__ f_W,
                 const float* __restrict__ f_b,
                 const float* __restrict__ e_W,
                 const float* __restrict__ e_b,
                 const float* __restrict__ a_W,
                 const float* __restrict__ a_b) {
    __shared__ __align__(16) float sbuf[16 * DK];    // 8KB, shared by roles
    int bid = blockIdx.x;
    int tid = threadIdx.x;

    if (bid < EA_BLOCKS) {
        // ---- pre_ea: (-e, a) for 16 rows ----
        int row0 = bid * 16;
        int j  = tid & 127;
        int rh = tid >> 7;                            // 2 halves x 8 rows
        #pragma unroll
        for (int u = 0; u < 2; u++) {
            int idx = tid + u * 256;                  // 512 float4 total
            reinterpret_cast<float4*>(sbuf)[idx] =
                __ldg(reinterpret_cast<const float4*>(v_emb + row0 * DV) + idx);
        }
        __syncthreads();

        float acce[8], acca[8];
        float eb = __ldg(e_b + j), ab = __ldg(a_b + j);
        #pragma unroll
        for (int r = 0; r < 8; r++) { acce[r] = eb; acca[r] = ab; }

        const float* xb = sbuf + rh * 8 * DV;
        #pragma unroll 4
        for (int k = 0; k < DV; k += 4) {
            float we0 = __ldg(e_W + (k + 0) * DV + j);
            float we1 = __ldg(e_W + (k + 1) * DV + j);
            float we2 = __ldg(e_W + (k + 2) * DV + j);
            float we3 = __ldg(e_W + (k + 3) * DV + j);
            float wa0 = __ldg(a_W + (k + 0) * DV + j);
            float wa1 = __ldg(a_W + (k + 1) * DV + j);
            float wa2 = __ldg(a_W + (k + 2) * DV + j);
            float wa3 = __ldg(a_W + (k + 3) * DV + j);
            #pragma unroll
            for (int r = 0; r < 8; r++) {
                float4 xv = *reinterpret_cast<const float4*>(xb + r * DV + k);
                acce[r] = fmaf(xv.x, we0, acce[r]);
                acce[r] = fmaf(xv.y, we1, acce[r]);
                acce[r] = fmaf(xv.z, we2, acce[r]);
                acce[r] = fmaf(xv.w, we3, acce[r]);
                acca[r] = fmaf(xv.x, wa0, acca[r]);
                acca[r] = fmaf(xv.y, wa1, acca[r]);
                acca[r] = fmaf(xv.z, wa2, acca[r]);
                acca[r] = fmaf(xv.w, wa3, acca[r]);
            }
        }
        #pragma unroll
        for (int r = 0; r < 8; r++) {
            int gr = row0 + rh * 8 + r;
            g_ea[gr * DV + j] = make_float2(-1.0f / (1.0f + expf(-acce[r])),
                                            tanhf(acca[r]));
        }
    } else if (bid < EA_BLOCKS + WT_BLOCKS) {
        // ---- pre_wt: softmax(k_emb @ Mk), one q per warp ----
        int warp = tid >> 5;
        int lane = tid & 31;
        int q = (bid - EA_BLOCKS) * 8 + warp;         // < 1000 exactly
        const float* krow = k_emb + q * DK;
        float acc = 0.f;
        #pragma unroll 8
        for (int k = 0; k < DK; k++)
            acc = fmaf(__ldg(krow + k), __ldg(Mk + k * CC + lane), acc);
        float mx = acc;
        #pragma unroll
        for (int off = 16; off; off >>= 1)
            mx = fmaxf(mx, __shfl_xor_sync(0xffffffffu, mx, off));
        float e = expf(acc - mx);
        float s = e;
        #pragma unroll
        for (int off = 16; off; off >>= 1)
            s += __shfl_xor_sync(0xffffffffu, s, off);
        g_wt[q * CC + lane] = e / s;
    } else if (bid < EA_BLOCKS + WT_BLOCKS + PG_BLOCKS) {
        // ---- pre_g: g = k_emb @ f_W[128:] + f_b, 16 rows ----
        int row0 = (bid - EA_BLOCKS - WT_BLOCKS) * 16;
        int j  = tid & 127;
        int rh = tid >> 7;                            // 2 halves x 8 rows
        #pragma unroll
        for (int u = 0; u < 2; u++) {
            int idx = tid + u * 256;                  // 512 float4 total
            int r   = idx >> 5;
            int gr  = row0 + r; if (gr >= NQ) gr = NQ - 1;
            reinterpret_cast<float4*>(sbuf)[idx] =
                __ldg(reinterpret_cast<const float4*>(k_emb + gr * DK) + (idx & 31));
        }
        __syncthreads();

        float acc[8];
        float fb = __ldg(f_b + j);
        #pragma unroll
        for (int r = 0; r < 8; r++) acc[r] = fb;

        const float* xb = sbuf + rh * 8 * DK;
        #pragma unroll 4
        for (int k = 0; k < DK; k += 4) {
            float w0 = __ldg(f_W + (DK + k + 0) * DK + j);
            float w1 = __ldg(f_W + (DK + k + 1) * DK + j);
            float w2 = __ldg(f_W + (DK + k + 2) * DK + j);
            float w3 = __ldg(f_W + (DK + k + 3) * DK + j);
            #pragma unroll
            for (int r = 0; r < 8; r++) {
                float4 xv = *reinterpret_cast<const float4*>(xb + r * DK + k);
                acc[r] = fmaf(xv.x, w0, acc[r]);
                acc[r] = fmaf(xv.y, w1, acc[r]);
                acc[r] = fmaf(xv.z, w2, acc[r]);
                acc[r] = fmaf(xv.w, w3, acc[r]);
            }
        }
        #pragma unroll
        for (int r = 0; r < 8; r++) {
            int gr = row0 + rh * 8 + r;
            if (gr < NQ) g_g[gr * DK + j] = acc[r];
        }
    } else {
        // ---- pre_pack: f_W lower half -> u64 i-pairs ----
        int idx = (bid - EA_BLOCKS - WT_BLOCKS - PG_BLOCKS) * 256 + tid;
        int ip = idx >> 7;
        int j  = idx & 127;
        g_fw2[idx] = pack2(__ldg(f_W + (2 * ip) * DK + j),
                           __ldg(f_W + (2 * ip + 1) * DK + j));
    }
}

// ---------------- sequential scan: 2 d-cols/thread, unroll-4 pipeline ------
// E-prefetch burst split across two step slots to avoid LSU queue spikes.

__device__ __forceinline__ void scan_loadW(int s, u64 W2[16]) {
    const ulonglong2* wp = reinterpret_cast<const ulonglong2*>(g_wt + s * CC);
    #pragma unroll
    for (int u = 0; u < 8; u++) {
        ulonglong2 v = __ldg(wp + u);
        W2[2 * u]     = v.x;
        W2[2 * u + 1] = v.y;
    }
}

__device__ __forceinline__ float scan_step(u64 m2[16], const u64 W2[16],
                                           float ne, float a) {
    u64 en2 = pack2(ne, ne);
    u64 a2  = pack2(a, a);
    u64 acc0 = 0ull, acc1 = 0ull;
    #pragma unroll
    for (int p = 0; p < 16; p++) {
        u64 mo = m2[p];
        if (p & 1) acc1 = fma2(W2[p], mo, acc1);
        else       acc0 = fma2(W2[p], mo, acc0);
        u64 tmp = fma2(mo, en2, a2);          // a - e*m
        m2[p] = fma2(W2[p], tmp, mo);         // m + w*(a - e*m)
    }
    float x0, x1, y0, y1;
    unpack2(acc0, x0, x1);
    unpack2(acc1, y0, y1);
    return (x0 + x1) + (y0 + y1);
}

__global__ void __launch_bounds__(128, 1)
scan_kernel(const int* __restrict__ skills,
            const int* __restrict__ responses,
            const float* __restrict__ Mv0) {
    int tid  = threadIdx.x;
    int half = tid >> 6;                 // 0/1 -> batch within block
    int td   = tid & 63;
    int b    = blockIdx.x * 2 + half;
    int d0   = td;
    int d1   = td + 64;

    u64 m0[16], m1[16];
    #pragma unroll
    for (int p = 0; p < 16; p++) {
        m0[p] = pack2(__ldg(Mv0 + (2 * p) * DV + d0),
                      __ldg(Mv0 + (2 * p + 1) * DV + d0));
        m1[p] = pack2(__ldg(Mv0 + (2 * p) * DV + d1),
                      __ldg(Mv0 + (2 * p + 1) * DV + d1));
    }

    const int* srow = skills + b * T;
    const int* rrow = responses + b * T;
    float* rtp0 = g_rt + (b * TOUT) * DV + d0;
    float* rtp1 = g_rt + (b * TOUT) * DV + d1;

    // staging for steps t..t+3
    int  s4[4];
    float2 E0[4], E1[4];
    #pragma unroll
    for (int k = 0; k < 4; k++) {
        int s = __ldg(srow + k);
        int q = s + NQ * __ldg(rrow + k);
        s4[k] = s;
        E0[k] = __ldg(g_ea + q * DV + d0);
        E1[k] = __ldg(g_ea + q * DV + d1);
    }
    u64 W0[16];
    scan_loadW(s4[0], W0);

    // main loop: t = 0,4,8,...,248  (63 bodies, steps 0..251)
    for (int t = 0; t < TOUT - 3; t += 4) {
        u64 W1[16], W2[16], W3[16];
        // staging for t+4..t+7 (t+7 <= 255, in range)
        int    ns[4];
        float2 nE0[4], nE1[4];

        scan_loadW(s4[1], W1);
        #pragma unroll
        for (int k = 0; k < 2; k++) {              // first half of E prefetch
            int s = __ldg(srow + t + 4 + k);
            int q = s + NQ * __ldg(rrow + t + 4 + k);
            ns[k]  = s;
            nE0[k] = __ldg(g_ea + q * DV + d0);
            nE1[k] = __ldg(g_ea + q * DV + d1);
        }
        rtp0[t * DV] = scan_step(m0, W0, E0[0].x, E0[0].y);
        rtp1[t * DV] = scan_step(m1, W0, E1[0].x, E1[0].y);

        scan_loadW(s4[2], W2);
        #pragma unroll
        for (int k = 2; k < 4; k++) {              // second half of E prefetch
            int s = __ldg(srow + t + 4 + k);
            int q = s + NQ * __ldg(rrow + t + 4 + k);
            ns[k]  = s;
            nE0[k] = __ldg(g_ea + q * DV + d0);
            nE1[k] = __ldg(g_ea + q * DV + d1);
        }
        rtp0[(t + 1) * DV] = scan_step(m0, W1, E0[1].x, E0[1].y);
        rtp1[(t + 1) * DV] = scan_step(m1, W1, E1[1].x, E1[1].y);

        scan_loadW(s4[3], W3);
        rtp0[(t + 2) * DV] = scan_step(m0, W2, E0[2].x, E0[2].y);
        rtp1[(t + 2) * DV] = scan_step(m1, W2, E1[2].x, E1[2].y);

        scan_loadW(ns[0], W0);              // W for t+4
        rtp0[(t + 3) * DV] = scan_step(m0, W3, E0[3].x, E0[3].y);
        rtp1[(t + 3) * DV] = scan_step(m1, W3, E1[3].x, E1[3].y);

        #pragma unroll
        for (int k = 0; k < 4; k++) {
            s4[k] = ns[k];
            E0[k] = nE0[k];
            E1[k] = nE1[k];
        }
    }

    // tail: steps 252, 253, 254 (data staged; s4/E hold 252..255)
    {
        u64 W1[16], W2[16];
        scan_loadW(s4[1], W1);
        rtp0[252 * DV] = scan_step(m0, W0, E0[0].x, E0[0].y);
        rtp1[252 * DV] = scan_step(m1, W0, E1[0].x, E1[0].y);
        scan_loadW(s4[2], W2);
        rtp0[253 * DV] = scan_step(m0, W1, E0[1].x, E0[1].y);
        rtp1[253 * DV] = scan_step(m1, W1, E1[1].x, E1[1].y);
        rtp0[254 * DV] = scan_step(m0, W2, E0[2].x, E0[2].y);
        rtp1[254 * DV] = scan_step(m1, W2, E1[2].x, E1[2].y);
    }
}

// ---------------- readout: GEMM + tanh + dot(p_W) + sigmoid ---------------
#define RT_ROWS 64
__global__ void __launch_bounds__(256)
readout_kernel(const float* __restrict__ p_W,
               const float* __restrict__ p_b,
               const int* __restrict__ skills,
               const int* __restrict__ responses,
               float* __restrict__ out,
               float* __restrict__ out2) {
    __shared__ __align__(16) float xs[RT_ROWS * DK];

    int tid  = threadIdx.x;
    int jg   = tid & 31;
    int rg   = tid >> 5;          // warp id 0..7
    int j0   = jg * 4;
    int row0 = blockIdx.x * RT_ROWS;

    {
        const float4* src = reinterpret_cast<const float4*>(g_rt + row0 * DK);
        float4* dst = reinterpret_cast<float4*>(xs);
        #pragma unroll
        for (int u = 0; u < (RT_ROWS * DK / 4) / 256; u++)
            dst[tid + u * 256] = src[tid + u * 256];
    }

    u64 acc2[8][4];
    #pragma unroll
    for (int r = 0; r < 8; r++) {
        int gr = row0 + rg * 8 + r;
        int bb = gr / TOUT;
        int tt = gr - bb * TOUT;
        int sk = __ldg(skills + bb * T + tt);
        float4 g = __ldg(reinterpret_cast<const float4*>(g_g + sk * DK + j0));
        acc2[r][0] = pack2(g.x, 0.f);
        acc2[r][1] = pack2(g.y, 0.f);
        acc2[r][2] = pack2(g.z, 0.f);
        acc2[r][3] = pack2(g.w, 0.f);
    }
    __syncthreads();

    const float* xb = xs + rg * 8 * DK;

    #pragma unroll 4
    for (int ip = 0; ip < DK / 2; ip++) {
        const ulonglong2* wp =
            reinterpret_cast<const ulonglong2*>(g_fw2 + ip * DK + j0);
        ulonglong2 wv0 = __ldg(wp);
        ulonglong2 wv1 = __ldg(wp + 1);
        #pragma unroll
        for (int r = 0; r < 8; r++) {
            u64 x2 = *reinterpret_cast<const u64*>(xb + r * DK + 2 * ip);
            acc2[r][0] = fma2(x2, wv0.x, acc2[r][0]);
            acc2[r][1] = fma2(x2, wv0.y, acc2[r][1]);
            acc2[r][2] = fma2(x2, wv1.x, acc2[r][2]);
            acc2[r][3] = fma2(x2, wv1.y, acc2[r][3]);
        }
    }

    float4 pw = __ldg(reinterpret_cast<const float4*>(p_W + j0));
    float pb  = __ldg(p_b);
    #pragma unroll
    for (int r = 0; r < 8; r++) {
        float l0, h0, l1, h1, l2, h2, l3, h3;
        unpack2(acc2[r][0], l0, h0);
        unpack2(acc2[r][1], l1, h1);
        unpack2(acc2[r][2], l2, h2);
        unpack2(acc2[r][3], l3, h3);
        float s = tanhf(l0 + h0) * pw.x + tanhf(l1 + h1) * pw.y
                + tanhf(l2 + h2) * pw.z + tanhf(l3 + h3) * pw.w;
        #pragma unroll
        for (int off = 16; off; off >>= 1)
            s += __shfl_xor_sync(0xffffffffu, s, off);
        if (jg == 0) {
            int gr = row0 + rg * 8 + r;
            out[gr] = 1.0f / (1.0f + expf(-s));
        }
    }

    if (tid < RT_ROWS) {
        int gr = row0 + tid;
        int bb = gr / TOUT;
        int tt = gr - bb * TOUT;
        out2[gr] = (float)__ldg(responses + bb * T + tt + 1);
    }
}

// ---------------- launch ----------------------------------------------------
extern "C" void kernel_launch(void* const* d_in, const int* in_sizes, int n_in,
                              void* d_out, int out_size) {
    const int*   skills    = (const int*)  d_in[0];
    const int*   responses = (const int*)  d_in[1];
    const float* k_emb     = (const float*)d_in[2];
    const float* v_emb     = (const float*)d_in[3];
    const float* Mk        = (const float*)d_in[4];
    const float* Mv0       = (const float*)d_in[5];
    const float* f_W       = (const float*)d_in[6];
    const float* f_b       = (const float*)d_in[7];
    const float* p_W       = (const float*)d_in[8];
    const float* p_b       = (const float*)d_in[9];
    const float* e_W       = (const float*)d_in[10];
    const float* e_b       = (const float*)d_in[11];
    const float* a_W       = (const float*)d_in[12];
    const float* a_b       = (const float*)d_in[13];

    float* pred_out = (float*)d_out;
    float* true_out = pred_out + (out_size / 2);

    pre_fused_kernel<<<PRE_BLOCKS, 256>>>(k_emb, v_emb, Mk, f_W, f_b,
                                          e_W, e_b, a_W, a_b);

    scan_kernel<<<B / 2, 128>>>(skills, responses, Mv0);

    readout_kernel<<<NROWS / RT_ROWS, 256>>>(p_W, p_b, skills, responses,
                                             pred_out, true_out);
}

// round 9
// speedup vs baseline: 1.3392x; 1.0413x over previous
#include <cuda_runtime.h>
#include <cuda_bf16.h>
#include <cstdint>

// Problem constants
#define B    256
#define T    256
#define NQ   1000
#define DK   128
#define DV   128
#define CC   32
#define TOUT 255
#define NROWS (B * TOUT)         // 65280

typedef unsigned long long u64;

// ---------------- packed f32x2 helpers (sm_103a) --------------------------
__device__ __forceinline__ u64 pack2(float lo, float hi) {
    u64 r; asm("mov.b64 %0, {%1, %2};" : "=l"(r) : "f"(lo), "f"(hi)); return r;
}
__device__ __forceinline__ void unpack2(u64 v, float& lo, float& hi) {
    asm("mov.b64 {%0, %1}, %2;" : "=f"(lo), "=f"(hi) : "l"(v));
}
__device__ __forceinline__ u64 fma2(u64 a, u64 b, u64 c) {
    u64 d; asm("fma.rn.f32x2 %0, %1, %2, %3;" : "=l"(d) : "l"(a), "l"(b), "l"(c)); return d;
}

// ---------------- device scratch ------------------------------------------
__device__ __align__(16) float  g_wt[NQ * CC];        // softmax(k_emb @ Mk)
__device__ __align__(16) float  g_g [NQ * DK];        // k_emb @ f_W[128:] + f_b
__device__ __align__(16) float2 g_ea[2 * NQ * DV];    // (-sigmoid(vW_e), tanh(vW_a))
__device__ __align__(16) float  g_rt[NROWS * DV];     // rt scratch
__device__ __align__(16) u64    g_fw2[(DK / 2) * DK]; // f_W rows 0..127, i-pair packed

// ---------------- fused precompute (round-7 version, measured 20.4us) ------
#define EA_BLOCKS 125
#define WT_BLOCKS 125
#define PG_BLOCKS 63
#define PK_BLOCKS 32
#define PRE_BLOCKS (EA_BLOCKS + WT_BLOCKS + PG_BLOCKS + PK_BLOCKS)

__global__ void __launch_bounds__(256)
pre_fused_kernel(const float* __restrict__ k_emb,
                 const float* __restrict__ v_emb,
                 const float* __restrict__ Mk,
                 const float* __restrict__ f_W,
                 const float* __restrict__ f_b,
                 const float* __restrict__ e_W,
                 const float* __restrict__ e_b,
                 const float* __restrict__ a_W,
                 const float* __restrict__ a_b) {
    __shared__ __align__(16) float sbuf[16 * DK];
    int bid = blockIdx.x;
    int tid = threadIdx.x;

    if (bid < EA_BLOCKS) {
        // ---- pre_ea: (-e, a) for 16 rows ----
        int row0 = bid * 16;
        int j  = tid & 127;
        int rh = tid >> 7;
        #pragma unroll
        for (int u = 0; u < 2; u++) {
            int idx = tid + u * 256;
            reinterpret_cast<float4*>(sbuf)[idx] =
                __ldg(reinterpret_cast<const float4*>(v_emb + row0 * DV) + idx);
        }
        __syncthreads();

        float acce[8], acca[8];
        float eb = __ldg(e_b + j), ab = __ldg(a_b + j);
        #pragma unroll
        for (int r = 0; r < 8; r++) { acce[r] = eb; acca[r] = ab; }

        const float* xb = sbuf + rh * 8 * DV;
        #pragma unroll 4
        for (int k = 0; k < DV; k += 4) {
            float we0 = __ldg(e_W + (k + 0) * DV + j);
            float we1 = __ldg(e_W + (k + 1) * DV + j);
            float we2 = __ldg(e_W + (k + 2) * DV + j);
            float we3 = __ldg(e_W + (k + 3) * DV + j);
            float wa0 = __ldg(a_W + (k + 0) * DV + j);
            float wa1 = __ldg(a_W + (k + 1) * DV + j);
            float wa2 = __ldg(a_W + (k + 2) * DV + j);
            float wa3 = __ldg(a_W + (k + 3) * DV + j);
            #pragma unroll
            for (int r = 0; r < 8; r++) {
                float4 xv = *reinterpret_cast<const float4*>(xb + r * DV + k);
                acce[r] = fmaf(xv.x, we0, acce[r]);
                acce[r] = fmaf(xv.y, we1, acce[r]);
                acce[r] = fmaf(xv.z, we2, acce[r]);
                acce[r] = fmaf(xv.w, we3, acce[r]);
                acca[r] = fmaf(xv.x, wa0, acca[r]);
                acca[r] = fmaf(xv.y, wa1, acca[r]);
                acca[r] = fmaf(xv.z, wa2, acca[r]);
                acca[r] = fmaf(xv.w, wa3, acca[r]);
            }
        }
        #pragma unroll
        for (int r = 0; r < 8; r++) {
            int gr = row0 + rh * 8 + r;
            g_ea[gr * DV + j] = make_float2(-1.0f / (1.0f + expf(-acce[r])),
                                            tanhf(acca[r]));
        }
    } else if (bid < EA_BLOCKS + WT_BLOCKS) {
        // ---- pre_wt: softmax(k_emb @ Mk), one q per warp ----
        int warp = tid >> 5;
        int lane = tid & 31;
        int q = (bid - EA_BLOCKS) * 8 + warp;
        const float* krow = k_emb + q * DK;
        float acc = 0.f;
        #pragma unroll 8
        for (int k = 0; k < DK; k++)
            acc = fmaf(__ldg(krow + k), __ldg(Mk + k * CC + lane), acc);
        float mx = acc;
        #pragma unroll
        for (int off = 16; off; off >>= 1)
            mx = fmaxf(mx, __shfl_xor_sync(0xffffffffu, mx, off));
        float e = expf(acc - mx);
        float s = e;
        #pragma unroll
        for (int off = 16; off; off >>= 1)
            s += __shfl_xor_sync(0xffffffffu, s, off);
        g_wt[q * CC + lane] = e / s;
    } else if (bid < EA_BLOCKS + WT_BLOCKS + PG_BLOCKS) {
        // ---- pre_g: g = k_emb @ f_W[128:] + f_b, 16 rows ----
        int row0 = (bid - EA_BLOCKS - WT_BLOCKS) * 16;
        int j  = tid & 127;
        int rh = tid >> 7;
        #pragma unroll
        for (int u = 0; u < 2; u++) {
            int idx = tid + u * 256;
            int r   = idx >> 5;
            int gr  = row0 + r; if (gr >= NQ) gr = NQ - 1;
            reinterpret_cast<float4*>(sbuf)[idx] =
                __ldg(reinterpret_cast<const float4*>(k_emb + gr * DK) + (idx & 31));
        }
        __syncthreads();

        float acc[8];
        float fb = __ldg(f_b + j);
        #pragma unroll
        for (int r = 0; r < 8; r++) acc[r] = fb;

        const float* xb = sbuf + rh * 8 * DK;
        #pragma unroll 4
        for (int k = 0; k < DK; k += 4) {
            float w0 = __ldg(f_W + (DK + k + 0) * DK + j);
            float w1 = __ldg(f_W + (DK + k + 1) * DK + j);
            float w2 = __ldg(f_W + (DK + k + 2) * DK + j);
            float w3 = __ldg(f_W + (DK + k + 3) * DK + j);
            #pragma unroll
            for (int r = 0; r < 8; r++) {
                float4 xv = *reinterpret_cast<const float4*>(xb + r * DK + k);
                acc[r] = fmaf(xv.x, w0, acc[r]);
                acc[r] = fmaf(xv.y, w1, acc[r]);
                acc[r] = fmaf(xv.z, w2, acc[r]);
                acc[r] = fmaf(xv.w, w3, acc[r]);
            }
        }
        #pragma unroll
        for (int r = 0; r < 8; r++) {
            int gr = row0 + rh * 8 + r;
            if (gr < NQ) g_g[gr * DK + j] = acc[r];
        }
    } else {
        // ---- pre_pack: f_W lower half -> u64 i-pairs ----
        int idx = (bid - EA_BLOCKS - WT_BLOCKS - PG_BLOCKS) * 256 + tid;
        int ip = idx >> 7;
        int j  = idx & 127;
        g_fw2[idx] = pack2(__ldg(f_W + (2 * ip) * DK + j),
                           __ldg(f_W + (2 * ip + 1) * DK + j));
    }
}

// ---------------- sequential scan: 2 d-cols/thread, unroll-8, 2 W bufs -----
// Register budget: m(64) + WA/WB(64) + E ring(32) + sE(8) + misc ~ 190 regs.
// W loaded 1 step ahead (L1 hit); E refilled in-place 8 steps ahead; the
// index pair for a refill is loaded one step before its use.

__device__ __forceinline__ void scan_loadW(int s, u64 W2[16]) {
    const ulonglong2* wp = reinterpret_cast<const ulonglong2*>(g_wt + s * CC);
    #pragma unroll
    for (int u = 0; u < 8; u++) {
        ulonglong2 v = __ldg(wp + u);
        W2[2 * u]     = v.x;
        W2[2 * u + 1] = v.y;
    }
}

__device__ __forceinline__ float scan_step(u64 m2[16], const u64 W2[16],
                                           float ne, float a) {
    u64 en2 = pack2(ne, ne);
    u64 a2  = pack2(a, a);
    u64 acc0 = 0ull, acc1 = 0ull;
    #pragma unroll
    for (int p = 0; p < 16; p++) {
        u64 mo = m2[p];
        if (p & 1) acc1 = fma2(W2[p], mo, acc1);
        else       acc0 = fma2(W2[p], mo, acc0);
        u64 tmp = fma2(mo, en2, a2);          // a - e*m
        m2[p] = fma2(W2[p], tmp, mo);         // m + w*(a - e*m)
    }
    float x0, x1, y0, y1;
    unpack2(acc0, x0, x1);
    unpack2(acc1, y0, y1);
    return (x0 + x1) + (y0 + y1);
}

__global__ void __launch_bounds__(128, 1)
scan_kernel(const int* __restrict__ skills,
            const int* __restrict__ responses,
            const float* __restrict__ Mv0) {
    int tid  = threadIdx.x;
    int half = tid >> 6;                 // 0/1 -> batch within block
    int td   = tid & 63;
    int b    = blockIdx.x * 2 + half;
    int d0   = td;
    int d1   = td + 64;

    u64 m0[16], m1[16];
    #pragma unroll
    for (int p = 0; p < 16; p++) {
        m0[p] = pack2(__ldg(Mv0 + (2 * p) * DV + d0),
                      __ldg(Mv0 + (2 * p + 1) * DV + d0));
        m1[p] = pack2(__ldg(Mv0 + (2 * p) * DV + d1),
                      __ldg(Mv0 + (2 * p + 1) * DV + d1));
    }

    const int* srow = skills + b * T;
    const int* rrow = responses + b * T;
    float* rtp0 = g_rt + (b * TOUT) * DV + d0;
    float* rtp1 = g_rt + (b * TOUT) * DV + d1;

    // E ring: slot k holds data for step (body_t + k); sE carries skill idx.
    int    sE[8];
    float2 E0[8], E1[8];
    #pragma unroll
    for (int k = 0; k < 8; k++) {
        int s = __ldg(srow + k);
        int q = s + NQ * __ldg(rrow + k);
        sE[k] = s;
        E0[k] = __ldg(g_ea + q * DV + d0);
        E1[k] = __ldg(g_ea + q * DV + d1);
    }
    // index pair for the first refill (step 8)
    int sCur = __ldg(srow + 8);
    int qCur = sCur + NQ * __ldg(rrow + 8);

    u64 WA[16], WB[16];
    scan_loadW(sE[0], WA);               // W for step 0

// One pipeline step: consume slot k with Wc, preload Wn for step t+k+1,
// refill slot k for step t+8+k, advance index pair to step t+9+k.
#define SCAN_BODY_STEP(k, Wc, Wn)                                          \
    {                                                                      \
        scan_loadW(sE[((k) + 1) & 7], Wn);                                 \
        rtp0[(t + (k)) * DV] = scan_step(m0, Wc, E0[k].x, E0[k].y);        \
        rtp1[(t + (k)) * DV] = scan_step(m1, Wc, E1[k].x, E1[k].y);        \
        E0[k] = __ldg(g_ea + qCur * DV + d0);                              \
        E1[k] = __ldg(g_ea + qCur * DV + d1);                              \
        sE[k] = sCur;                                                      \
        int ni = t + 9 + (k); if (ni > T - 1) ni = T - 1;                  \
        sCur = __ldg(srow + ni);                                           \
        qCur = sCur + NQ * __ldg(rrow + ni);                               \
    }

    // 31 bodies: steps 0..247
    for (int t = 0; t < 248; t += 8) {
        SCAN_BODY_STEP(0, WA, WB)
        SCAN_BODY_STEP(1, WB, WA)
        SCAN_BODY_STEP(2, WA, WB)
        SCAN_BODY_STEP(3, WB, WA)
        SCAN_BODY_STEP(4, WA, WB)
        SCAN_BODY_STEP(5, WB, WA)
        SCAN_BODY_STEP(6, WA, WB)
        SCAN_BODY_STEP(7, WB, WA)
    }
#undef SCAN_BODY_STEP

    // tail: steps 248..254 (slots 0..6; WA holds W(248) from last body)
    {
        const int t = 248;
#define SCAN_TAIL_STEP(k, Wc, Wn)                                          \
        {                                                                  \
            scan_loadW(sE[(k) + 1], Wn);                                   \
            rtp0[(t + (k)) * DV] = scan_step(m0, Wc, E0[k].x, E0[k].y);    \
            rtp1[(t + (k)) * DV] = scan_step(m1, Wc, E1[k].x, E1[k].y);    \
        }
        SCAN_TAIL_STEP(0, WA, WB)
        SCAN_TAIL_STEP(1, WB, WA)
        SCAN_TAIL_STEP(2, WA, WB)
        SCAN_TAIL_STEP(3, WB, WA)
        SCAN_TAIL_STEP(4, WA, WB)
        SCAN_TAIL_STEP(5, WB, WA)
        // step 254: no next W needed
        rtp0[254 * DV] = scan_step(m0, WA, E0[6].x, E0[6].y);
        rtp1[254 * DV] = scan_step(m1, WA, E1[6].x, E1[6].y);
#undef SCAN_TAIL_STEP
    }
}

// ---------------- readout: GEMM + tanh + dot(p_W) + sigmoid (round-7) ------
#define RT_ROWS 64
__global__ void __launch_bounds__(256)
readout_kernel(const float* __restrict__ p_W,
               const float* __restrict__ p_b,
               const int* __restrict__ skills,
               const int* __restrict__ responses,
               float* __restrict__ out,
               float* __restrict__ out2) {
    __shared__ __align__(16) float xs[RT_ROWS * DK];

    int tid  = threadIdx.x;
    int jg   = tid & 31;
    int rg   = tid >> 5;          // warp id 0..7
    int j0   = jg * 4;
    int row0 = blockIdx.x * RT_ROWS;

    {
        const float4* src = reinterpret_cast<const float4*>(g_rt + row0 * DK);
        float4* dst = reinterpret_cast<float4*>(xs);
        #pragma unroll
        for (int u = 0; u < (RT_ROWS * DK / 4) / 256; u++)
            dst[tid + u * 256] = src[tid + u * 256];
    }

    u64 acc2[8][4];
    #pragma unroll
    for (int r = 0; r < 8; r++) {
        int gr = row0 + rg * 8 + r;
        int bb = gr / TOUT;
        int tt = gr - bb * TOUT;
        int sk = __ldg(skills + bb * T + tt);
        float4 g = __ldg(reinterpret_cast<const float4*>(g_g + sk * DK + j0));
        acc2[r][0] = pack2(g.x, 0.f);
        acc2[r][1] = pack2(g.y, 0.f);
        acc2[r][2] = pack2(g.z, 0.f);
        acc2[r][3] = pack2(g.w, 0.f);
    }
    __syncthreads();

    const float* xb = xs + rg * 8 * DK;

    #pragma unroll 4
    for (int ip = 0; ip < DK / 2; ip++) {
        const ulonglong2* wp =
            reinterpret_cast<const ulonglong2*>(g_fw2 + ip * DK + j0);
        ulonglong2 wv0 = __ldg(wp);
        ulonglong2 wv1 = __ldg(wp + 1);
        #pragma unroll
        for (int r = 0; r < 8; r++) {
            u64 x2 = *reinterpret_cast<const u64*>(xb + r * DK + 2 * ip);
            acc2[r][0] = fma2(x2, wv0.x, acc2[r][0]);
            acc2[r][1] = fma2(x2, wv0.y, acc2[r][1]);
            acc2[r][2] = fma2(x2, wv1.x, acc2[r][2]);
            acc2[r][3] = fma2(x2, wv1.y, acc2[r][3]);
        }
    }

    float4 pw = __ldg(reinterpret_cast<const float4*>(p_W + j0));
    float pb  = __ldg(p_b);
    #pragma unroll
    for (int r = 0; r < 8; r++) {
        float l0, h0, l1, h1, l2, h2, l3, h3;
        unpack2(acc2[r][0], l0, h0);
        unpack2(acc2[r][1], l1, h1);
        unpack2(acc2[r][2], l2, h2);
        unpack2(acc2[r][3], l3, h3);
        float s = tanhf(l0 + h0) * pw.x + tanhf(l1 + h1) * pw.y
                + tanhf(l2 + h2) * pw.z + tanhf(l3 + h3) * pw.w;
        #pragma unroll
        for (int off = 16; off; off >>= 1)
            s += __shfl_xor_sync(0xffffffffu, s, off);
        if (jg == 0) {
            int gr = row0 + rg * 8 + r;
            out[gr] = 1.0f / (1.0f + expf(-s));
        }
    }

    if (tid < RT_ROWS) {
        int gr = row0 + tid;
        int bb = gr / TOUT;
        int tt = gr - bb * TOUT;
        out2[gr] = (float)__ldg(responses + bb * T + tt + 1);
    }
}

// ---------------- launch ----------------------------------------------------
extern "C" void kernel_launch(void* const* d_in, const int* in_sizes, int n_in,
                              void* d_out, int out_size) {
    const int*   skills    = (const int*)  d_in[0];
    const int*   responses = (const int*)  d_in[1];
    const float* k_emb     = (const float*)d_in[2];
    const float* v_emb     = (const float*)d_in[3];
    const float* Mk        = (const float*)d_in[4];
    const float* Mv0       = (const float*)d_in[5];
    const float* f_W       = (const float*)d_in[6];
    const float* f_b       = (const float*)d_in[7];
    const float* p_W       = (const float*)d_in[8];
    const float* p_b       = (const float*)d_in[9];
    const float* e_W       = (const float*)d_in[10];
    const float* e_b       = (const float*)d_in[11];
    const float* a_W       = (const float*)d_in[12];
    const float* a_b       = (const float*)d_in[13];

    float* pred_out = (float*)d_out;
    float* true_out = pred_out + (out_size / 2);

    pre_fused_kernel<<<PRE_BLOCKS, 256>>>(k_emb, v_emb, Mk, f_W, f_b,
                                          e_W, e_b, a_W, a_b);

    scan_kernel<<<B / 2, 128>>>(skills, responses, Mv0);

    readout_kernel<<<NROWS / RT_ROWS, 256>>>(p_W, p_b, skills, responses,
                                             pred_out, true_out);
}